// round 4
// baseline (speedup 1.0000x reference)
#include <cuda_runtime.h>
#include <math.h>

// Problem dims
#define BB 8
#define SS 512
#define DD 256
#define HH 8
#define DHH 32
#define NBLK 8
#define TOK (BB*SS)          // 4096 tokens

// ---------------- device scratch (no allocation allowed) ----------------
__device__ float g_buf1[TOK * 4096];   // 64 MB ping
__device__ float g_buf2[TOK * 2048];   // 32 MB pong
__device__ float g_x  [TOK * DD];
__device__ float g_xn [TOK * DD];
__device__ float g_qkv[TOK * 3 * DD];
__device__ float g_att[TOK * DD];
__device__ float g_h  [TOK * 1024];
__device__ double g_red[2];
__device__ float g_stats[2];

// ---------------- GEMM: C[M,N] = act(A[M,K] @ W[K,N] + bias (+rowadd)) ----------------
// ACT: 0=none 1=relu 2=tanh 3=gelu(exact). ACCUM: C += result. ADDROW: add rowadd[(row%SS)*N+col]
template<int BM, int BN, int BK, int TM, int TN, int ACT, bool ACCUM, bool ADDROW>
__global__ void gemm_k(const float* __restrict__ A, const float* __restrict__ W,
                       const float* __restrict__ bias, const float* __restrict__ rowadd,
                       float* __restrict__ C, int M, int N, int K)
{
    constexpr int TX = BN / TN;                 // threads along N
    constexpr int TY = BM / TM;                 // threads along M
    static_assert(TX * TY == 256, "256 threads");
    __shared__ float As[BK][BM];
    __shared__ float Bs[BK][BN];

    const int tid = threadIdx.x;
    const int tx = tid % TX, ty = tid / TX;
    const int bm = blockIdx.y * BM, bn = blockIdx.x * BN;

    float acc[TM][TN];
#pragma unroll
    for (int i = 0; i < TM; i++)
#pragma unroll
        for (int j = 0; j < TN; j++) acc[i][j] = 0.f;

    constexpr int A_V4_PER_ROW = BK / 4;
    constexpr int A_ITERS = (BM * BK / 4) / 256;
    constexpr int B_V4_PER_ROW = BN / 4;
    constexpr int B_ITERS = (BK * BN / 4) / 256;

    const float* Aptr = A + (size_t)bm * K;
    const float* Bptr = W + bn;

    for (int k0 = 0; k0 < K; k0 += BK) {
#pragma unroll
        for (int it = 0; it < A_ITERS; it++) {
            int idx = tid + it * 256;
            int row = idx / A_V4_PER_ROW;
            int c4  = idx % A_V4_PER_ROW;
            float4 v = *reinterpret_cast<const float4*>(Aptr + (size_t)row * K + k0 + c4 * 4);
            As[c4*4+0][row] = v.x; As[c4*4+1][row] = v.y;
            As[c4*4+2][row] = v.z; As[c4*4+3][row] = v.w;
        }
#pragma unroll
        for (int it = 0; it < B_ITERS; it++) {
            int idx = tid + it * 256;
            int row = idx / B_V4_PER_ROW;
            int c4  = idx % B_V4_PER_ROW;
            *reinterpret_cast<float4*>(&Bs[row][c4*4]) =
                *reinterpret_cast<const float4*>(Bptr + (size_t)(k0 + row) * N + c4 * 4);
        }
        __syncthreads();

#pragma unroll
        for (int k = 0; k < BK; k++) {
            float ar[TM], br[TN];
#pragma unroll
            for (int i = 0; i < TM / 4; i++) {
                float4 t4 = *reinterpret_cast<const float4*>(&As[k][ty * TM + i * 4]);
                ar[i*4+0] = t4.x; ar[i*4+1] = t4.y; ar[i*4+2] = t4.z; ar[i*4+3] = t4.w;
            }
#pragma unroll
            for (int j = 0; j < TN / 4; j++) {
                float4 t4 = *reinterpret_cast<const float4*>(&Bs[k][tx * TN + j * 4]);
                br[j*4+0] = t4.x; br[j*4+1] = t4.y; br[j*4+2] = t4.z; br[j*4+3] = t4.w;
            }
#pragma unroll
            for (int i = 0; i < TM; i++)
#pragma unroll
                for (int j = 0; j < TN; j++)
                    acc[i][j] = fmaf(ar[i], br[j], acc[i][j]);
        }
        __syncthreads();
    }

#pragma unroll
    for (int i = 0; i < TM; i++) {
        int row = bm + ty * TM + i;
#pragma unroll
        for (int j = 0; j < TN; j++) {
            int col = bn + tx * TN + j;
            float v = acc[i][j] + bias[col];
            if (ADDROW) v += rowadd[(size_t)(row % SS) * N + col];
            if (ACT == 1) v = fmaxf(v, 0.f);
            else if (ACT == 2) v = tanhf(v);
            else if (ACT == 3) v = 0.5f * v * (1.f + erff(v * 0.70710678118654752f));
            float* cp = C + (size_t)row * N + col;
            if (ACCUM) *cp += v; else *cp = v;
        }
    }
}

// ---------------- LayerNorm over D=256 per token; optional residual add, in/out-of-place ----------------
template<bool ADD>
__global__ void ln_k(const float* __restrict__ x, const float* __restrict__ add,
                     const float* __restrict__ g, const float* __restrict__ b,
                     float* __restrict__ out)
{
    int t = blockIdx.x;
    int tid = threadIdx.x;    // 256 threads == D
    float v = x[(size_t)t * DD + tid];
    if (ADD) v += add[(size_t)t * DD + tid];

    float s = v, q = v * v;
#pragma unroll
    for (int o = 16; o > 0; o >>= 1) {
        s += __shfl_xor_sync(0xffffffffu, s, o);
        q += __shfl_xor_sync(0xffffffffu, q, o);
    }
    __shared__ float ws[8], wq[8];
    int w = tid >> 5, lane = tid & 31;
    if (lane == 0) { ws[w] = s; wq[w] = q; }
    __syncthreads();
    if (tid == 0) {
        float ts = 0.f, tq = 0.f;
#pragma unroll
        for (int i = 0; i < 8; i++) { ts += ws[i]; tq += wq[i]; }
        ws[0] = ts; wq[0] = tq;
    }
    __syncthreads();
    float mean = ws[0] * (1.f / DD);
    float var  = wq[0] * (1.f / DD) - mean * mean;
    float r = rsqrtf(var + 1e-5f);
    out[(size_t)t * DD + tid] = (v - mean) * r * g[tid] + b[tid];
}

// ---------------- Causal attention: one block per (b, h, q-row), 128 threads ----------------
__global__ void attn_k(const float* __restrict__ qkv, float* __restrict__ att)
{
    int idx = blockIdx.x;                 // b*H*S + h*S + q
    int q = idx % SS;
    int h = (idx / SS) % HH;
    int b = idx / (SS * HH);
    int tid = threadIdx.x;                // 128

    __shared__ float qs[DHH];
    __shared__ float sc[SS];
    __shared__ float red[128];

    const float* base = qkv + (size_t)(b * SS) * (3 * DD);
    if (tid < DHH) qs[tid] = base[(size_t)q * (3 * DD) + h * DHH + tid];
    __syncthreads();

    const float scale = rsqrtf((float)DHH);
    float lmax = -1e30f;
    for (int j = tid; j <= q; j += 128) {
        const float* krow = base + (size_t)j * (3 * DD) + DD + h * DHH;
        float dot = 0.f;
#pragma unroll
        for (int d = 0; d < DHH; d++) dot = fmaf(qs[d], krow[d], dot);
        dot *= scale;
        sc[j] = dot;
        lmax = fmaxf(lmax, dot);
    }
    red[tid] = lmax;
    __syncthreads();
#pragma unroll
    for (int s = 64; s > 0; s >>= 1) {
        if (tid < s) red[tid] = fmaxf(red[tid], red[tid + s]);
        __syncthreads();
    }
    float m = red[0];
    __syncthreads();

    float lsum = 0.f;
    for (int j = tid; j <= q; j += 128) {
        float e = expf(sc[j] - m);
        sc[j] = e;
        lsum += e;
    }
    red[tid] = lsum;
    __syncthreads();
#pragma unroll
    for (int s = 64; s > 0; s >>= 1) {
        if (tid < s) red[tid] += red[tid + s];
        __syncthreads();
    }
    float inv = 1.f / red[0];
    __syncthreads();

    // weighted sum of V: 4 chunks x 32 dims
    int d = tid & 31, c = tid >> 5;
    float acc = 0.f;
    for (int j = c; j <= q; j += 4) {
        acc = fmaf(sc[j], base[(size_t)j * (3 * DD) + 2 * DD + h * DHH + d], acc);
    }
    red[tid] = acc;
    __syncthreads();
    if (c == 0) {
        float v = red[d] + red[32 + d] + red[64 + d] + red[96 + d];
        att[(size_t)(b * SS + q) * DD + h * DHH + d] = v * inv;
    }
}

// ---------------- global normalize (mean / std ddof=1, + 1e-10) ----------------
__global__ void zero_red_k() { g_red[0] = 0.0; g_red[1] = 0.0; }

__global__ void reduce_k(const float* __restrict__ x, int n)
{
    double s = 0.0, q = 0.0;
    for (int i = blockIdx.x * blockDim.x + threadIdx.x; i < n; i += gridDim.x * blockDim.x) {
        double v = (double)x[i];
        s += v; q += v * v;
    }
#pragma unroll
    for (int o = 16; o > 0; o >>= 1) {
        s += __shfl_xor_sync(0xffffffffu, s, o);
        q += __shfl_xor_sync(0xffffffffu, q, o);
    }
    __shared__ double ws[8], wq[8];
    int w = threadIdx.x >> 5, lane = threadIdx.x & 31;
    if (lane == 0) { ws[w] = s; wq[w] = q; }
    __syncthreads();
    if (threadIdx.x == 0) {
        double ts = 0.0, tq = 0.0;
        for (int i = 0; i < (int)(blockDim.x / 32); i++) { ts += ws[i]; tq += wq[i]; }
        atomicAdd(&g_red[0], ts);
        atomicAdd(&g_red[1], tq);
    }
}

__global__ void stats_k(int n)
{
    double mean = g_red[0] / n;
    double var = (g_red[1] - (double)n * mean * mean) / (double)(n - 1);
    g_stats[0] = (float)mean;
    g_stats[1] = (float)(1.0 / sqrt(var));
}

__global__ void norm_k(float* __restrict__ x, int n)
{
    int i = blockIdx.x * blockDim.x + threadIdx.x;
    if (i < n) x[i] = (x[i] - g_stats[0]) * g_stats[1] + 1e-10f;
}

// ---------------- host-side launch helpers ----------------
template<int ACT, bool ACCUM, bool ADDROW>
static void gemm_big(const float* A, const float* W, const float* b, const float* ra,
                     float* C, int M, int N, int K)
{
    gemm_k<128, 128, 16, 8, 8, ACT, ACCUM, ADDROW><<<dim3(N / 128, M / 128), 256>>>(A, W, b, ra, C, M, N, K);
}
template<int ACT, bool ACCUM, bool ADDROW>
static void gemm_small(const float* A, const float* W, const float* b, const float* ra,
                       float* C, int M, int N, int K)
{
    gemm_k<64, 64, 16, 4, 4, ACT, ACCUM, ADDROW><<<dim3(N / 64, M / 64), 256>>>(A, W, b, ra, C, M, N, K);
}

extern "C" void kernel_launch(void* const* d_in, const int* in_sizes, int n_in,
                              void* d_out, int out_size)
{
    const float* state  = (const float*)d_in[0];
    const float* fc1_w  = (const float*)d_in[1];
    const float* fc1_b  = (const float*)d_in[2];
    const float* fc2_w  = (const float*)d_in[3];
    const float* fc2_b  = (const float*)d_in[4];
    const float* fc3_w  = (const float*)d_in[5];
    const float* fc3_b  = (const float*)d_in[6];
    const float* fc4_w  = (const float*)d_in[7];
    const float* fc4_b  = (const float*)d_in[8];
    const float* fc5_w  = (const float*)d_in[9];
    const float* fc5_b  = (const float*)d_in[10];
    const float* pre_w  = (const float*)d_in[11];
    const float* pre_b  = (const float*)d_in[12];
    const float* pos_w  = (const float*)d_in[13];
    const float* enc_w  = (const float*)d_in[14];
    const float* enc_b  = (const float*)d_in[15];
    const float* ln1_g  = (const float*)d_in[16];
    const float* ln1_b  = (const float*)d_in[17];
    const float* ln2_g  = (const float*)d_in[18];
    const float* ln2_b  = (const float*)d_in[19];
    const float* res_w1 = (const float*)d_in[20];
    const float* res_b1 = (const float*)d_in[21];
    const float* res_w2 = (const float*)d_in[22];
    const float* res_b2 = (const float*)d_in[23];
    const float* out_w  = (const float*)d_in[24];
    const float* out_b  = (const float*)d_in[25];
    float* out = (float*)d_out;

    float *buf1, *buf2, *x, *xn, *qkv, *att, *h;
    cudaGetSymbolAddress((void**)&buf1, g_buf1);
    cudaGetSymbolAddress((void**)&buf2, g_buf2);
    cudaGetSymbolAddress((void**)&x,    g_x);
    cudaGetSymbolAddress((void**)&xn,   g_xn);
    cudaGetSymbolAddress((void**)&qkv,  g_qkv);
    cudaGetSymbolAddress((void**)&att,  g_att);
    cudaGetSymbolAddress((void**)&h,    g_h);

    const int M = TOK;

    // MLP stack
    gemm_big<1, false, false>(state, fc1_w, fc1_b, nullptr, buf1, M, 4096, 4096);
    gemm_big<1, false, false>(buf1,  fc2_w, fc2_b, nullptr, buf2, M, 2048, 4096);
    gemm_big<1, false, false>(buf2,  fc3_w, fc3_b, nullptr, buf1, M, 1024, 2048);
    gemm_big<1, false, false>(buf1,  fc4_w, fc4_b, nullptr, buf2, M,  512, 1024);
    gemm_small<2, false, false>(buf2, fc5_w, fc5_b, nullptr, buf1, M, DD, 512);
    // pre projection + positional add
    gemm_small<0, false, true>(buf1, pre_w, pre_b, pos_w, x, M, DD, DD);

    // transformer blocks
    for (int l = 0; l < NBLK; l++) {
        ln_k<false><<<TOK, 256>>>(x, nullptr, ln1_g + l * DD, ln1_b + l * DD, xn);
        gemm_big<0, false, false>(xn, enc_w + (size_t)l * DD * 3 * DD, enc_b + l * 3 * DD,
                                  nullptr, qkv, M, 3 * DD, DD);
        attn_k<<<BB * HH * SS, 128>>>(qkv, att);
        ln_k<true><<<TOK, 256>>>(x, att, ln2_g + l * DD, ln2_b + l * DD, x);
        gemm_big<3, false, false>(x, res_w1 + (size_t)l * DD * 4 * DD, res_b1 + l * 4 * DD,
                                  nullptr, h, M, 4 * DD, DD);
        gemm_small<0, true, false>(h, res_w2 + (size_t)l * 4 * DD * DD, res_b2 + l * DD,
                                   nullptr, x, M, DD, 4 * DD);
    }

    // output projection + global normalize
    gemm_small<0, false, false>(x, out_w, out_b, nullptr, out, M, 128, DD);
    int n = TOK * 128;
    zero_red_k<<<1, 1>>>();
    reduce_k<<<256, 256>>>(out, n);
    stats_k<<<1, 1>>>(n);
    norm_k<<<(n + 255) / 256, 256>>>(out, n);
}

// round 6
// speedup vs baseline: 1.1568x; 1.1568x over previous
#include <cuda_runtime.h>
#include <cuda_bf16.h>
#include <math.h>
#include <stdint.h>

// Problem dims
#define BB 8
#define SS 512
#define DD 256
#define HH 8
#define DHH 32
#define NBLK 8
#define TOK (BB*SS)          // 4096 tokens

// ---------------- device scratch (no allocation allowed) ----------------
__device__ float g_buf1[TOK * 4096];   // 64 MB ping
__device__ float g_buf2[TOK * 2048];   // 32 MB pong
__device__ float g_x  [TOK * DD];
__device__ float g_xn [TOK * DD];
__device__ float g_qkv[TOK * 3 * DD];
__device__ float g_att[TOK * DD];
__device__ float g_h  [TOK * 1024];
__device__ double g_red[2];
__device__ float g_stats[2];

// ---------------- bf16 split helpers ----------------
__device__ __forceinline__ void split_pair(float x, float y, uint32_t& hi, uint32_t& lo)
{
    __nv_bfloat16 hx = __float2bfloat16_rn(x);
    __nv_bfloat16 hy = __float2bfloat16_rn(y);
    float rx = x - __bfloat162float(hx);
    float ry = y - __bfloat162float(hy);
    __nv_bfloat162 h2; h2.x = hx; h2.y = hy;
    __nv_bfloat162 l2; l2.x = __float2bfloat16_rn(rx); l2.y = __float2bfloat16_rn(ry);
    hi = *reinterpret_cast<uint32_t*>(&h2);
    lo = *reinterpret_cast<uint32_t*>(&l2);
}

__device__ __forceinline__ void mma16816(float* c, const uint32_t* a, const uint32_t* b)
{
    asm volatile(
        "mma.sync.aligned.m16n8k16.row.col.f32.bf16.bf16.f32 "
        "{%0,%1,%2,%3},{%4,%5,%6,%7},{%8,%9},{%0,%1,%2,%3};"
        : "+f"(c[0]), "+f"(c[1]), "+f"(c[2]), "+f"(c[3])
        : "r"(a[0]), "r"(a[1]), "r"(a[2]), "r"(a[3]), "r"(b[0]), "r"(b[1]));
}

// ---------------- tensor-core GEMM: C[M,N] = act(A @ W + bias (+rowadd)) ----------------
// bf16x3 split precision (hi*hi + hi*lo + lo*hi), fp32 accumulate.
// ACT: 0=none 1=relu 2=tanh 3=gelu(exact). ACCUM: C += result. ADDROW: add rowadd[(row%SS)*N+col]
template<int BM, int BN, int WY, int WX, int ACT, bool ACCUM, bool ADDROW>
__global__ __launch_bounds__(256, 1)
void gemm_tc(const float* __restrict__ A, const float* __restrict__ W,
             const float* __restrict__ bias, const float* __restrict__ rowadd,
             float* __restrict__ C, int M, int N, int K)
{
    constexpr int BK = 32;             // K per stage
    constexpr int KP = BK / 2;         // 16 bf162 pairs per row
    constexpr int ST = KP + 4;         // row stride 20 u32: conflict-free
    constexpr int WTM = BM / WY;       // warp tile M
    constexpr int WTN = BN / WX;       // warp tile N
    constexpr int MT = WTM / 16;
    constexpr int NT = WTN / 8;
    constexpr int AI  = (BM * 8) / 256;         // float4 A loads / thread
    constexpr int BIU = (KP * (BN / 4)) / 256;  // B pair-units / thread (2 float4 each)
    static_assert(WY * WX == 8, "8 warps");

    __shared__ uint32_t Ah[BM][ST], Al[BM][ST];
    __shared__ uint32_t Bh[BN][ST], Bl[BN][ST];

    const int tid  = threadIdx.x;
    const int lane = tid & 31;
    const int warp = tid >> 5;
    const int wy = warp / WX, wx = warp % WX;
    const int bm = blockIdx.y * BM, bn = blockIdx.x * BN;
    const int g = lane >> 2, t4 = lane & 3;

    float acc[MT][NT][4];
#pragma unroll
    for (int i = 0; i < MT; i++)
#pragma unroll
        for (int j = 0; j < NT; j++)
#pragma unroll
            for (int r = 0; r < 4; r++) acc[i][j][r] = 0.f;

    float4 aR[AI], bR0[BIU], bR1[BIU];

    // --- global load stage k0 into registers ---
    auto ldg = [&](int k0) {
#pragma unroll
        for (int it = 0; it < AI; it++) {
            int idx = tid + it * 256;
            int r = idx >> 3, c4 = idx & 7;
            aR[it] = *reinterpret_cast<const float4*>(A + (size_t)(bm + r) * K + k0 + c4 * 4);
        }
#pragma unroll
        for (int it = 0; it < BIU; it++) {
            int idx = tid + it * 256;
            int kp = idx / (BN / 4), nq = idx % (BN / 4);
            const float* p = W + (size_t)(k0 + 2 * kp) * N + bn + nq * 4;
            bR0[it] = *reinterpret_cast<const float4*>(p);
            bR1[it] = *reinterpret_cast<const float4*>(p + N);
        }
    };

    // --- registers -> shared (with bf16 hi/lo split) ---
    auto sts = [&]() {
#pragma unroll
        for (int it = 0; it < AI; it++) {
            int idx = tid + it * 256;
            int r = idx >> 3, c4 = idx & 7;
            uint32_t h0, l0, h1, l1;
            split_pair(aR[it].x, aR[it].y, h0, l0);
            split_pair(aR[it].z, aR[it].w, h1, l1);
            Ah[r][c4 * 2]     = h0;  Al[r][c4 * 2]     = l0;
            Ah[r][c4 * 2 + 1] = h1;  Al[r][c4 * 2 + 1] = l1;
        }
#pragma unroll
        for (int it = 0; it < BIU; it++) {
            int idx = tid + it * 256;
            int kp = idx / (BN / 4), nq = idx % (BN / 4);
            float f0[4] = { bR0[it].x, bR0[it].y, bR0[it].z, bR0[it].w };
            float f1[4] = { bR1[it].x, bR1[it].y, bR1[it].z, bR1[it].w };
#pragma unroll
            for (int j = 0; j < 4; j++) {
                uint32_t h, l;
                split_pair(f0[j], f1[j], h, l);
                Bh[nq * 4 + j][kp] = h;
                Bl[nq * 4 + j][kp] = l;
            }
        }
    };

    // --- compute one BK=32 stage from shared ---
    auto compute = [&]() {
#pragma unroll
        for (int kk = 0; kk < 2; kk++) {
            const int kpo = kk * 8;
            uint32_t ah[MT][4], al[MT][4], bh[NT][2], bl[NT][2];
#pragma unroll
            for (int mt = 0; mt < MT; mt++) {
                int m0 = wy * WTM + mt * 16;
                ah[mt][0] = Ah[m0 + g    ][kpo + t4];
                ah[mt][1] = Ah[m0 + 8 + g][kpo + t4];
                ah[mt][2] = Ah[m0 + g    ][kpo + t4 + 4];
                ah[mt][3] = Ah[m0 + 8 + g][kpo + t4 + 4];
                al[mt][0] = Al[m0 + g    ][kpo + t4];
                al[mt][1] = Al[m0 + 8 + g][kpo + t4];
                al[mt][2] = Al[m0 + g    ][kpo + t4 + 4];
                al[mt][3] = Al[m0 + 8 + g][kpo + t4 + 4];
            }
#pragma unroll
            for (int nt = 0; nt < NT; nt++) {
                int n0 = wx * WTN + nt * 8 + g;
                bh[nt][0] = Bh[n0][kpo + t4];
                bh[nt][1] = Bh[n0][kpo + t4 + 4];
                bl[nt][0] = Bl[n0][kpo + t4];
                bl[nt][1] = Bl[n0][kpo + t4 + 4];
            }
#pragma unroll
            for (int mt = 0; mt < MT; mt++)
#pragma unroll
                for (int nt = 0; nt < NT; nt++) {
                    mma16816(acc[mt][nt], ah[mt], bh[nt]);  // hi*hi
                    mma16816(acc[mt][nt], ah[mt], bl[nt]);  // hi*lo
                    mma16816(acc[mt][nt], al[mt], bh[nt]);  // lo*hi
                }
        }
    };

    ldg(0);
    for (int k0 = 0; k0 < K; k0 += BK) {
        __syncthreads();
        sts();
        __syncthreads();
        if (k0 + BK < K) ldg(k0 + BK);   // prefetch next stage during compute
        compute();
    }

    // --- epilogue ---
    auto epi = [&](int row, int col, float v0, float v1) {
        v0 += bias[col]; v1 += bias[col + 1];
        if (ADDROW) {
            const float* ra = rowadd + (size_t)(row % SS) * N + col;
            v0 += ra[0]; v1 += ra[1];
        }
        if (ACT == 1) { v0 = fmaxf(v0, 0.f); v1 = fmaxf(v1, 0.f); }
        else if (ACT == 2) { v0 = tanhf(v0); v1 = tanhf(v1); }
        else if (ACT == 3) {
            v0 = 0.5f * v0 * (1.f + erff(v0 * 0.70710678118654752f));
            v1 = 0.5f * v1 * (1.f + erff(v1 * 0.70710678118654752f));
        }
        float* cp = C + (size_t)row * N + col;
        if (ACCUM) { cp[0] += v0; cp[1] += v1; }
        else       { float2 o; o.x = v0; o.y = v1; *reinterpret_cast<float2*>(cp) = o; }
    };

#pragma unroll
    for (int mt = 0; mt < MT; mt++) {
        int r0 = bm + wy * WTM + mt * 16 + g;
#pragma unroll
        for (int nt = 0; nt < NT; nt++) {
            int c = bn + wx * WTN + nt * 8 + t4 * 2;
            epi(r0,     c, acc[mt][nt][0], acc[mt][nt][1]);
            epi(r0 + 8, c, acc[mt][nt][2], acc[mt][nt][3]);
        }
    }
}

// ---------------- LayerNorm over D=256 per token ----------------
template<bool ADD>
__global__ void ln_k(const float* __restrict__ x, const float* __restrict__ add,
                     const float* __restrict__ g, const float* __restrict__ b,
                     float* __restrict__ out)
{
    int t = blockIdx.x;
    int tid = threadIdx.x;    // 256 threads == D
    float v = x[(size_t)t * DD + tid];
    if (ADD) v += add[(size_t)t * DD + tid];

    float s = v, q = v * v;
#pragma unroll
    for (int o = 16; o > 0; o >>= 1) {
        s += __shfl_xor_sync(0xffffffffu, s, o);
        q += __shfl_xor_sync(0xffffffffu, q, o);
    }
    __shared__ float ws[8], wq[8];
    int w = tid >> 5, lane = tid & 31;
    if (lane == 0) { ws[w] = s; wq[w] = q; }
    __syncthreads();
    if (tid == 0) {
        float ts = 0.f, tq = 0.f;
#pragma unroll
        for (int i = 0; i < 8; i++) { ts += ws[i]; tq += wq[i]; }
        ws[0] = ts; wq[0] = tq;
    }
    __syncthreads();
    float mean = ws[0] * (1.f / DD);
    float var  = wq[0] * (1.f / DD) - mean * mean;
    float r = rsqrtf(var + 1e-5f);
    out[(size_t)t * DD + tid] = (v - mean) * r * g[tid] + b[tid];
}

// ---------------- Causal attention: one block per (b, h, q-row) ----------------
__global__ void attn_k(const float* __restrict__ qkv, float* __restrict__ att)
{
    int idx = blockIdx.x;                 // b*H*S + h*S + q
    int q = idx % SS;
    int h = (idx / SS) % HH;
    int b = idx / (SS * HH);
    int tid = threadIdx.x;                // 128

    __shared__ float qs[DHH];
    __shared__ float sc[SS];
    __shared__ float red[128];

    const float* base = qkv + (size_t)(b * SS) * (3 * DD);
    if (tid < DHH) qs[tid] = base[(size_t)q * (3 * DD) + h * DHH + tid];
    __syncthreads();

    const float scale = rsqrtf((float)DHH);
    float lmax = -1e30f;
    for (int j = tid; j <= q; j += 128) {
        const float* krow = base + (size_t)j * (3 * DD) + DD + h * DHH;
        float dot = 0.f;
#pragma unroll
        for (int d = 0; d < DHH; d++) dot = fmaf(qs[d], krow[d], dot);
        dot *= scale;
        sc[j] = dot;
        lmax = fmaxf(lmax, dot);
    }
    red[tid] = lmax;
    __syncthreads();
#pragma unroll
    for (int s = 64; s > 0; s >>= 1) {
        if (tid < s) red[tid] = fmaxf(red[tid], red[tid + s]);
        __syncthreads();
    }
    float m = red[0];
    __syncthreads();

    float lsum = 0.f;
    for (int j = tid; j <= q; j += 128) {
        float e = expf(sc[j] - m);
        sc[j] = e;
        lsum += e;
    }
    red[tid] = lsum;
    __syncthreads();
#pragma unroll
    for (int s = 64; s > 0; s >>= 1) {
        if (tid < s) red[tid] += red[tid + s];
        __syncthreads();
    }
    float inv = 1.f / red[0];
    __syncthreads();

    int d = tid & 31, c = tid >> 5;
    float acc = 0.f;
    for (int j = c; j <= q; j += 4) {
        acc = fmaf(sc[j], base[(size_t)j * (3 * DD) + 2 * DD + h * DHH + d], acc);
    }
    red[tid] = acc;
    __syncthreads();
    if (c == 0) {
        float v = red[d] + red[32 + d] + red[64 + d] + red[96 + d];
        att[(size_t)(b * SS + q) * DD + h * DHH + d] = v * inv;
    }
}

// ---------------- global normalize (mean / std ddof=1, + 1e-10) ----------------
__global__ void zero_red_k() { g_red[0] = 0.0; g_red[1] = 0.0; }

__global__ void reduce_k(const float* __restrict__ x, int n)
{
    double s = 0.0, q = 0.0;
    for (int i = blockIdx.x * blockDim.x + threadIdx.x; i < n; i += gridDim.x * blockDim.x) {
        double v = (double)x[i];
        s += v; q += v * v;
    }
#pragma unroll
    for (int o = 16; o > 0; o >>= 1) {
        s += __shfl_xor_sync(0xffffffffu, s, o);
        q += __shfl_xor_sync(0xffffffffu, q, o);
    }
    __shared__ double ws[8], wq[8];
    int w = threadIdx.x >> 5, lane = threadIdx.x & 31;
    if (lane == 0) { ws[w] = s; wq[w] = q; }
    __syncthreads();
    if (threadIdx.x == 0) {
        double ts = 0.0, tq = 0.0;
        for (int i = 0; i < (int)(blockDim.x / 32); i++) { ts += ws[i]; tq += wq[i]; }
        atomicAdd(&g_red[0], ts);
        atomicAdd(&g_red[1], tq);
    }
}

__global__ void stats_k(int n)
{
    double mean = g_red[0] / n;
    double var = (g_red[1] - (double)n * mean * mean) / (double)(n - 1);
    g_stats[0] = (float)mean;
    g_stats[1] = (float)(1.0 / sqrt(var));
}

__global__ void norm_k(float* __restrict__ x, int n)
{
    int i = blockIdx.x * blockDim.x + threadIdx.x;
    if (i < n) x[i] = (x[i] - g_stats[0]) * g_stats[1] + 1e-10f;
}

// ---------------- host-side launch helpers ----------------
template<int ACT, bool ACCUM, bool ADDROW>
static void gemm128(const float* A, const float* W, const float* b, const float* ra,
                    float* C, int M, int N, int K)
{
    gemm_tc<128, 128, 2, 4, ACT, ACCUM, ADDROW><<<dim3(N / 128, M / 128), 256>>>(A, W, b, ra, C, M, N, K);
}
template<int ACT, bool ACCUM, bool ADDROW>
static void gemm64(const float* A, const float* W, const float* b, const float* ra,
                   float* C, int M, int N, int K)
{
    gemm_tc<64, 128, 1, 8, ACT, ACCUM, ADDROW><<<dim3(N / 128, M / 64), 256>>>(A, W, b, ra, C, M, N, K);
}

extern "C" void kernel_launch(void* const* d_in, const int* in_sizes, int n_in,
                              void* d_out, int out_size)
{
    const float* state  = (const float*)d_in[0];
    const float* fc1_w  = (const float*)d_in[1];
    const float* fc1_b  = (const float*)d_in[2];
    const float* fc2_w  = (const float*)d_in[3];
    const float* fc2_b  = (const float*)d_in[4];
    const float* fc3_w  = (const float*)d_in[5];
    const float* fc3_b  = (const float*)d_in[6];
    const float* fc4_w  = (const float*)d_in[7];
    const float* fc4_b  = (const float*)d_in[8];
    const float* fc5_w  = (const float*)d_in[9];
    const float* fc5_b  = (const float*)d_in[10];
    const float* pre_w  = (const float*)d_in[11];
    const float* pre_b  = (const float*)d_in[12];
    const float* pos_w  = (const float*)d_in[13];
    const float* enc_w  = (const float*)d_in[14];
    const float* enc_b  = (const float*)d_in[15];
    const float* ln1_g  = (const float*)d_in[16];
    const float* ln1_b  = (const float*)d_in[17];
    const float* ln2_g  = (const float*)d_in[18];
    const float* ln2_b  = (const float*)d_in[19];
    const float* res_w1 = (const float*)d_in[20];
    const float* res_b1 = (const float*)d_in[21];
    const float* res_w2 = (const float*)d_in[22];
    const float* res_b2 = (const float*)d_in[23];
    const float* out_w  = (const float*)d_in[24];
    const float* out_b  = (const float*)d_in[25];
    float* out = (float*)d_out;

    float *buf1, *buf2, *x, *xn, *qkv, *att, *h;
    cudaGetSymbolAddress((void**)&buf1, g_buf1);
    cudaGetSymbolAddress((void**)&buf2, g_buf2);
    cudaGetSymbolAddress((void**)&x,    g_x);
    cudaGetSymbolAddress((void**)&xn,   g_xn);
    cudaGetSymbolAddress((void**)&qkv,  g_qkv);
    cudaGetSymbolAddress((void**)&att,  g_att);
    cudaGetSymbolAddress((void**)&h,    g_h);

    const int M = TOK;

    // MLP stack (tensor cores, bf16x3)
    gemm128<1, false, false>(state, fc1_w, fc1_b, nullptr, buf1, M, 4096, 4096);
    gemm128<1, false, false>(buf1,  fc2_w, fc2_b, nullptr, buf2, M, 2048, 4096);
    gemm128<1, false, false>(buf2,  fc3_w, fc3_b, nullptr, buf1, M, 1024, 2048);
    gemm128<1, false, false>(buf1,  fc4_w, fc4_b, nullptr, buf2, M,  512, 1024);
    gemm64 <2, false, false>(buf2,  fc5_w, fc5_b, nullptr, buf1, M, DD, 512);
    // pre projection + positional add
    gemm64 <0, false, true >(buf1,  pre_w, pre_b, pos_w,   x,    M, DD, DD);

    // transformer blocks
    for (int l = 0; l < NBLK; l++) {
        ln_k<false><<<TOK, 256>>>(x, nullptr, ln1_g + l * DD, ln1_b + l * DD, xn);
        gemm128<0, false, false>(xn, enc_w + (size_t)l * DD * 3 * DD, enc_b + l * 3 * DD,
                                 nullptr, qkv, M, 3 * DD, DD);
        attn_k<<<BB * HH * SS, 128>>>(qkv, att);
        ln_k<true><<<TOK, 256>>>(x, att, ln2_g + l * DD, ln2_b + l * DD, x);
        gemm128<3, false, false>(x, res_w1 + (size_t)l * DD * 4 * DD, res_b1 + l * 4 * DD,
                                 nullptr, h, M, 4 * DD, DD);
        gemm64 <0, true, false>(h, res_w2 + (size_t)l * 4 * DD * DD, res_b2 + l * DD,
                                nullptr, x, M, DD, 4 * DD);
    }

    // output projection + global normalize
    gemm64<0, false, false>(x, out_w, out_b, nullptr, out, M, 128, DD);
    int n = TOK * 128;
    zero_red_k<<<1, 1>>>();
    reduce_k<<<256, 256>>>(out, n);
    stats_k<<<1, 1>>>(n);
    norm_k<<<(n + 255) / 256, 256>>>(out, n);
}

// round 7
// speedup vs baseline: 2.4634x; 2.1295x over previous
#include <cuda_runtime.h>
#include <cuda_bf16.h>
#include <math.h>
#include <stdint.h>

// Problem dims
#define BB 8
#define SS 512
#define DD 256
#define HH 8
#define DHH 32
#define NBLK 8
#define TOK (BB*SS)          // 4096 tokens

// ---------------- device scratch ----------------
// weight split arena (u32 = bf16x2 pairs along K), layout [K/2][N]
#define W1_OFF   0u
#define W1_SZ    (2048u*4096u)
#define W2_OFF   (W1_OFF + W1_SZ)
#define W2_SZ    (2048u*2048u)
#define W3_OFF   (W2_OFF + W2_SZ)
#define W3_SZ    (1024u*1024u)
#define W4_OFF   (W3_OFF + W3_SZ)
#define W4_SZ    (512u*512u)
#define W5_OFF   (W4_OFF + W4_SZ)
#define W5_SZ    (256u*256u)
#define WPRE_OFF (W5_OFF + W5_SZ)
#define WPRE_SZ  (128u*256u)
#define WENC_OFF (WPRE_OFF + WPRE_SZ)
#define WENC_SZ  (1024u*768u)
#define WR1_OFF  (WENC_OFF + WENC_SZ)
#define WR1_SZ   (1024u*1024u)
#define WR2_OFF  (WR1_OFF + WR1_SZ)
#define WR2_SZ   (4096u*256u)
#define WOUT_OFF (WR2_OFF + WR2_SZ)
#define WOUT_SZ  (128u*128u)
#define WARENA   (WOUT_OFF + WOUT_SZ)

__device__ uint32_t g_wh[WARENA];
__device__ uint32_t g_wl[WARENA];

// activation split ping-pong arenas: [M][K/2] u32, max 4096 x 2048
__device__ uint32_t g_ah1[4096u*2048u];
__device__ uint32_t g_al1[4096u*2048u];
__device__ uint32_t g_ah2[4096u*2048u];
__device__ uint32_t g_al2[4096u*2048u];

__device__ float g_x  [TOK * DD];
__device__ float g_qkv[TOK * 3 * DD];
__device__ float g_att[TOK * DD];
__device__ double g_red[2];
__device__ float g_stats[2];

// ---------------- bf16 split helpers ----------------
__device__ __forceinline__ void split_pair(float x, float y, uint32_t& hi, uint32_t& lo)
{
    __nv_bfloat16 hx = __float2bfloat16_rn(x);
    __nv_bfloat16 hy = __float2bfloat16_rn(y);
    float rx = x - __bfloat162float(hx);
    float ry = y - __bfloat162float(hy);
    __nv_bfloat162 h2; h2.x = hx; h2.y = hy;
    __nv_bfloat162 l2; l2.x = __float2bfloat16_rn(rx); l2.y = __float2bfloat16_rn(ry);
    hi = *reinterpret_cast<uint32_t*>(&h2);
    lo = *reinterpret_cast<uint32_t*>(&l2);
}

__device__ __forceinline__ void mma16816(float* c, const uint32_t* a, const uint32_t* b)
{
    asm volatile(
        "mma.sync.aligned.m16n8k16.row.col.f32.bf16.bf16.f32 "
        "{%0,%1,%2,%3},{%4,%5,%6,%7},{%8,%9},{%0,%1,%2,%3};"
        : "+f"(c[0]), "+f"(c[1]), "+f"(c[2]), "+f"(c[3])
        : "r"(a[0]), "r"(a[1]), "r"(a[2]), "r"(a[3]), "r"(b[0]), "r"(b[1]));
}

// ---------------- split kernels ----------------
// weight: fp32 [K][N] -> hi/lo u32 [K/2][N]
__global__ void wsplit_k(const float* __restrict__ W, uint32_t* __restrict__ hi,
                         uint32_t* __restrict__ lo, int K2, int N)
{
    int idx = blockIdx.x * blockDim.x + threadIdx.x;
    if (idx >= K2 * N) return;
    int kp = idx / N, n = idx % N;
    float f0 = W[(size_t)(2 * kp) * N + n];
    float f1 = W[(size_t)(2 * kp + 1) * N + n];
    uint32_t h, l;
    split_pair(f0, f1, h, l);
    hi[idx] = h; lo[idx] = l;
}

// activation: fp32 row-major, pairs along K
__global__ void asplit_k(const float* __restrict__ A, uint32_t* __restrict__ hi,
                         uint32_t* __restrict__ lo, int total)
{
    int idx = blockIdx.x * blockDim.x + threadIdx.x;
    if (idx >= total) return;
    float2 v = reinterpret_cast<const float2*>(A)[idx];
    uint32_t h, l;
    split_pair(v.x, v.y, h, l);
    hi[idx] = h; lo[idx] = l;
}

// ---------------- tensor-core GEMM, bf16x3 split operands in global ----------------
// A: hi/lo [M][K2], B: hi/lo [K2][N].  C = act(A@B + bias (+rowadd))
// OMODE: 0 = write fp32 C, 1 = write split Chi/Clo [M][N/2]
template<int BM, int BN, int WY, int WX, int ACT, int OMODE, bool ACCUM, bool ADDROW>
__global__ __launch_bounds__(256, 1)
void gemm_bs(const uint32_t* __restrict__ Ahg, const uint32_t* __restrict__ Alg,
             const uint32_t* __restrict__ Bhg, const uint32_t* __restrict__ Blg,
             const float* __restrict__ bias, const float* __restrict__ rowadd,
             float* __restrict__ C, uint32_t* __restrict__ Chi, uint32_t* __restrict__ Clo,
             int M, int N, int K2)
{
    constexpr int KP = 16;               // K-pairs per stage (K=32)
    constexpr int ST = KP + 4;           // row stride 20 u32 (conflict-free)
    constexpr int WTM = BM / WY;
    constexpr int WTN = BN / WX;
    constexpr int MT = WTM / 16;
    constexpr int NT = WTN / 8;
    constexpr int AI4 = (BM * KP / 4) / 256;   // uint4 A loads/thread/array
    constexpr int BI4 = (KP * BN / 4) / 256;   // uint4 B loads/thread/array
    constexpr int SZ = (2 * BM + 2 * BN) * ST; // u32 per stage
    static_assert(WY * WX == 8, "8 warps");

    extern __shared__ uint32_t sm[];

    const int tid  = threadIdx.x;
    const int lane = tid & 31;
    const int warp = tid >> 5;
    const int wy = warp / WX, wx = warp % WX;
    const int bm = blockIdx.y * BM, bn = blockIdx.x * BN;
    const int g = lane >> 2, t4 = lane & 3;

    float acc[MT][NT][4];
#pragma unroll
    for (int i = 0; i < MT; i++)
#pragma unroll
        for (int j = 0; j < NT; j++)
#pragma unroll
            for (int r = 0; r < 4; r++) acc[i][j][r] = 0.f;

    uint4 aH[AI4], aL[AI4], bH[BI4], bL[BI4];

    auto ldg = [&](int s) {
        const int k2 = s * KP;
#pragma unroll
        for (int it = 0; it < AI4; it++) {
            int idx = tid + it * 256;
            int r = idx / (KP / 4), c = idx % (KP / 4);
            size_t off = (size_t)(bm + r) * K2 + k2 + c * 4;
            aH[it] = *reinterpret_cast<const uint4*>(Ahg + off);
            aL[it] = *reinterpret_cast<const uint4*>(Alg + off);
        }
#pragma unroll
        for (int it = 0; it < BI4; it++) {
            int idx = tid + it * 256;
            int kp = idx / (BN / 4), nq = idx % (BN / 4);
            size_t off = (size_t)(k2 + kp) * N + bn + nq * 4;
            bH[it] = *reinterpret_cast<const uint4*>(Bhg + off);
            bL[it] = *reinterpret_cast<const uint4*>(Blg + off);
        }
    };

    auto sts = [&](int buf) {
        uint32_t* sAh = sm + buf * SZ;
        uint32_t* sAl = sAh + BM * ST;
        uint32_t* sBh = sAl + BM * ST;
        uint32_t* sBl = sBh + BN * ST;
#pragma unroll
        for (int it = 0; it < AI4; it++) {
            int idx = tid + it * 256;
            int r = idx / (KP / 4), c = idx % (KP / 4);
            *reinterpret_cast<uint4*>(sAh + r * ST + c * 4) = aH[it];
            *reinterpret_cast<uint4*>(sAl + r * ST + c * 4) = aL[it];
        }
#pragma unroll
        for (int it = 0; it < BI4; it++) {
            int idx = tid + it * 256;
            int kp = idx / (BN / 4), nq = idx % (BN / 4);
            sBh[(nq * 4 + 0) * ST + kp] = bH[it].x;
            sBh[(nq * 4 + 1) * ST + kp] = bH[it].y;
            sBh[(nq * 4 + 2) * ST + kp] = bH[it].z;
            sBh[(nq * 4 + 3) * ST + kp] = bH[it].w;
            sBl[(nq * 4 + 0) * ST + kp] = bL[it].x;
            sBl[(nq * 4 + 1) * ST + kp] = bL[it].y;
            sBl[(nq * 4 + 2) * ST + kp] = bL[it].z;
            sBl[(nq * 4 + 3) * ST + kp] = bL[it].w;
        }
    };

    auto compute = [&](int buf) {
        const uint32_t* sAh = sm + buf * SZ;
        const uint32_t* sAl = sAh + BM * ST;
        const uint32_t* sBh = sAl + BM * ST;
        const uint32_t* sBl = sBh + BN * ST;
#pragma unroll
        for (int kk = 0; kk < 2; kk++) {
            const int kpo = kk * 8;
            uint32_t ah[MT][4], al[MT][4], bh[NT][2], bl[NT][2];
#pragma unroll
            for (int mt = 0; mt < MT; mt++) {
                int m0 = wy * WTM + mt * 16;
                ah[mt][0] = sAh[(m0 + g    ) * ST + kpo + t4];
                ah[mt][1] = sAh[(m0 + 8 + g) * ST + kpo + t4];
                ah[mt][2] = sAh[(m0 + g    ) * ST + kpo + t4 + 4];
                ah[mt][3] = sAh[(m0 + 8 + g) * ST + kpo + t4 + 4];
                al[mt][0] = sAl[(m0 + g    ) * ST + kpo + t4];
                al[mt][1] = sAl[(m0 + 8 + g) * ST + kpo + t4];
                al[mt][2] = sAl[(m0 + g    ) * ST + kpo + t4 + 4];
                al[mt][3] = sAl[(m0 + 8 + g) * ST + kpo + t4 + 4];
            }
#pragma unroll
            for (int nt = 0; nt < NT; nt++) {
                int n0 = wx * WTN + nt * 8 + g;
                bh[nt][0] = sBh[n0 * ST + kpo + t4];
                bh[nt][1] = sBh[n0 * ST + kpo + t4 + 4];
                bl[nt][0] = sBl[n0 * ST + kpo + t4];
                bl[nt][1] = sBl[n0 * ST + kpo + t4 + 4];
            }
#pragma unroll
            for (int mt = 0; mt < MT; mt++)
#pragma unroll
                for (int nt = 0; nt < NT; nt++) {
                    mma16816(acc[mt][nt], ah[mt], bh[nt]);  // hi*hi
                    mma16816(acc[mt][nt], ah[mt], bl[nt]);  // hi*lo
                    mma16816(acc[mt][nt], al[mt], bh[nt]);  // lo*hi
                }
        }
    };

    const int NS = K2 / KP;
    ldg(0);
    sts(0);
    __syncthreads();
    for (int s = 0; s < NS; s++) {
        if (s + 1 < NS) ldg(s + 1);
        compute(s & 1);
        if (s + 1 < NS) {
            sts((s + 1) & 1);
            __syncthreads();
        }
    }

    // --- epilogue: pairs (col, col+1) ---
    auto epi = [&](int row, int col, float v0, float v1) {
        v0 += bias[col]; v1 += bias[col + 1];
        if (ADDROW) {
            const float* ra = rowadd + (size_t)(row % SS) * N + col;
            v0 += ra[0]; v1 += ra[1];
        }
        if (ACT == 1) { v0 = fmaxf(v0, 0.f); v1 = fmaxf(v1, 0.f); }
        else if (ACT == 2) { v0 = tanhf(v0); v1 = tanhf(v1); }
        else if (ACT == 3) {
            v0 = 0.5f * v0 * (1.f + erff(v0 * 0.70710678118654752f));
            v1 = 0.5f * v1 * (1.f + erff(v1 * 0.70710678118654752f));
        }
        if (OMODE == 0) {
            float* cp = C + (size_t)row * N + col;
            if (ACCUM) { cp[0] += v0; cp[1] += v1; }
            else       { float2 o; o.x = v0; o.y = v1; *reinterpret_cast<float2*>(cp) = o; }
        } else {
            uint32_t h, l;
            split_pair(v0, v1, h, l);
            size_t pi = (size_t)row * (N / 2) + col / 2;
            Chi[pi] = h; Clo[pi] = l;
        }
    };

#pragma unroll
    for (int mt = 0; mt < MT; mt++) {
        int r0 = bm + wy * WTM + mt * 16 + g;
#pragma unroll
        for (int nt = 0; nt < NT; nt++) {
            int c = bn + wx * WTN + nt * 8 + t4 * 2;
            epi(r0,     c, acc[mt][nt][0], acc[mt][nt][1]);
            epi(r0 + 8, c, acc[mt][nt][2], acc[mt][nt][3]);
        }
    }
}

// ---------------- LayerNorm over D=256, 128 threads x float2 ----------------
template<bool ADD, bool WF, bool WS>
__global__ void ln_k(const float* __restrict__ x, const float* __restrict__ add,
                     const float* __restrict__ g, const float* __restrict__ b,
                     float* __restrict__ outf, uint32_t* __restrict__ ohi,
                     uint32_t* __restrict__ olo)
{
    int t = blockIdx.x;
    int tid = threadIdx.x;    // 128
    float2 v = reinterpret_cast<const float2*>(x + (size_t)t * DD)[tid];
    if (ADD) {
        float2 a2 = reinterpret_cast<const float2*>(add + (size_t)t * DD)[tid];
        v.x += a2.x; v.y += a2.y;
    }
    float s = v.x + v.y, q = v.x * v.x + v.y * v.y;
#pragma unroll
    for (int o = 16; o > 0; o >>= 1) {
        s += __shfl_xor_sync(0xffffffffu, s, o);
        q += __shfl_xor_sync(0xffffffffu, q, o);
    }
    __shared__ float ws[4], wq[4];
    int w = tid >> 5, lane = tid & 31;
    if (lane == 0) { ws[w] = s; wq[w] = q; }
    __syncthreads();
    float ts = ws[0] + ws[1] + ws[2] + ws[3];
    float tq = wq[0] + wq[1] + wq[2] + wq[3];
    float mean = ts * (1.f / DD);
    float var  = tq * (1.f / DD) - mean * mean;
    float r = rsqrtf(var + 1e-5f);
    float2 gg = reinterpret_cast<const float2*>(g)[tid];
    float2 bb = reinterpret_cast<const float2*>(b)[tid];
    float y0 = (v.x - mean) * r * gg.x + bb.x;
    float y1 = (v.y - mean) * r * gg.y + bb.y;
    if (WF) {
        float2 o; o.x = y0; o.y = y1;
        reinterpret_cast<float2*>(outf + (size_t)t * DD)[tid] = o;
    }
    if (WS) {
        uint32_t h, l;
        split_pair(y0, y1, h, l);
        ohi[(size_t)t * (DD / 2) + tid] = h;
        olo[(size_t)t * (DD / 2) + tid] = l;
    }
}

// ---------------- flash-style causal attention ----------------
// grid (S/128, H, B), 256 threads: 2 threads per q-row (half = tid&1, 32 k each per 64-ktile)
__global__ __launch_bounds__(256, 2)
void attn_k(const float* __restrict__ qkv, float* __restrict__ att)
{
    constexpr int KT = 64;
    constexpr int VST = 36;   // smem row stride (floats), 16B-aligned, bank-spread
    __shared__ float Ks[KT * VST];
    __shared__ float Vs[KT * VST];

    const int qt = blockIdx.x, h = blockIdx.y, b = blockIdx.z;
    const int tid = threadIdx.x;
    const int r = tid >> 1, half = tid & 1;
    const int qg = qt * 128 + r;

    const float* base = qkv + (size_t)(b * SS) * (3 * DD);
    const float scale = rsqrtf((float)DHH);

    // Q row in registers (scaled)
    float qreg[DHH];
    {
        const float4* qp = reinterpret_cast<const float4*>(base + (size_t)qg * (3 * DD) + h * DHH);
#pragma unroll
        for (int i = 0; i < 8; i++) {
            float4 f = qp[i];
            qreg[i*4+0] = f.x * scale; qreg[i*4+1] = f.y * scale;
            qreg[i*4+2] = f.z * scale; qreg[i*4+3] = f.w * scale;
        }
    }

    float m = -1e30f, lsum = 0.f;
    float o[DHH];
#pragma unroll
    for (int d = 0; d < DHH; d++) o[d] = 0.f;

    const int ntiles = (qt + 1) * 2;
    for (int kt = 0; kt < ntiles; kt++) {
        // cooperative load K,V tile (64 rows x 32 floats = 512 float4 each)
#pragma unroll
        for (int it = 0; it < 2; it++) {
            int idx = tid + it * 256;
            int rr = idx >> 3, c = idx & 7;
            int k = kt * KT + rr;
            const float4* kp = reinterpret_cast<const float4*>(base + (size_t)k * (3 * DD) + DD + h * DHH);
            const float4* vp = reinterpret_cast<const float4*>(base + (size_t)k * (3 * DD) + 2 * DD + h * DHH);
            *reinterpret_cast<float4*>(&Ks[rr * VST + c * 4]) = kp[c];
            *reinterpret_cast<float4*>(&Vs[rr * VST + c * 4]) = vp[c];
        }
        __syncthreads();

        const int kbase = kt * KT + half * 32;
        if (kbase <= qg) {
            float p[32];
            float smax = -1e30f;
#pragma unroll 4
            for (int kk = 0; kk < 32; kk++) {
                const float* kr = &Ks[(half * 32 + kk) * VST];
                float dot = 0.f;
#pragma unroll
                for (int d = 0; d < DHH; d++) dot = fmaf(qreg[d], kr[d], dot);
                if (kbase + kk > qg) dot = -1e30f;
                p[kk] = dot;
                smax = fmaxf(smax, dot);
            }
            float newm = fmaxf(m, smax);
            float f = __expf(m - newm);
            float ls = 0.f;
#pragma unroll
            for (int kk = 0; kk < 32; kk++) {
                p[kk] = __expf(p[kk] - newm);
                ls += p[kk];
            }
            lsum = lsum * f + ls;
#pragma unroll
            for (int d = 0; d < DHH; d++) o[d] *= f;
#pragma unroll 4
            for (int kk = 0; kk < 32; kk++) {
                const float* vr = &Vs[(half * 32 + kk) * VST];
                float pk = p[kk];
#pragma unroll
                for (int d = 0; d < DHH; d++) o[d] = fmaf(pk, vr[d], o[d]);
            }
            m = newm;
        }
        __syncthreads();
    }

    // merge the two halves of each q-row (lanes differ by 1)
    float om = __shfl_xor_sync(0xffffffffu, m, 1);
    float nm = fmaxf(m, om);
    float fs = __expf(m - nm);
    float lS = lsum * fs;
    float lT = lS + __shfl_xor_sync(0xffffffffu, lS, 1);
    float inv = 1.f / lT;
    float* op = att + (size_t)(b * SS + qg) * DD + h * DHH;
#pragma unroll
    for (int d = 0; d < DHH; d++) {
        float oS = o[d] * fs;
        float oT = oS + __shfl_xor_sync(0xffffffffu, oS, 1);
        if (half == 0) op[d] = oT * inv;
    }
}

// ---------------- global normalize (mean / std ddof=1, + 1e-10) ----------------
__global__ void zero_red_k() { g_red[0] = 0.0; g_red[1] = 0.0; }

__global__ void reduce_k(const float* __restrict__ x, int n)
{
    double s = 0.0, q = 0.0;
    for (int i = blockIdx.x * blockDim.x + threadIdx.x; i < n; i += gridDim.x * blockDim.x) {
        double v = (double)x[i];
        s += v; q += v * v;
    }
#pragma unroll
    for (int o = 16; o > 0; o >>= 1) {
        s += __shfl_xor_sync(0xffffffffu, s, o);
        q += __shfl_xor_sync(0xffffffffu, q, o);
    }
    __shared__ double ws[8], wq[8];
    int w = threadIdx.x >> 5, lane = threadIdx.x & 31;
    if (lane == 0) { ws[w] = s; wq[w] = q; }
    __syncthreads();
    if (threadIdx.x == 0) {
        double ts = 0.0, tq = 0.0;
        for (int i = 0; i < (int)(blockDim.x / 32); i++) { ts += ws[i]; tq += wq[i]; }
        atomicAdd(&g_red[0], ts);
        atomicAdd(&g_red[1], tq);
    }
}

__global__ void stats_k(int n)
{
    double mean = g_red[0] / n;
    double var = (g_red[1] - (double)n * mean * mean) / (double)(n - 1);
    g_stats[0] = (float)mean;
    g_stats[1] = (float)(1.0 / sqrt(var));
}

__global__ void norm_k(float* __restrict__ x, int n)
{
    int i = blockIdx.x * blockDim.x + threadIdx.x;
    if (i < n) x[i] = (x[i] - g_stats[0]) * g_stats[1] + 1e-10f;
}

// ---------------- host-side launch helpers ----------------
template<int BM, int WY, int WX, int ACT, int OMODE, bool ACCUM, bool ADDROW>
static void launch_gemm(const uint32_t* Ah, const uint32_t* Al,
                        const uint32_t* Bh, const uint32_t* Bl,
                        const float* bias, const float* ra,
                        float* C, uint32_t* Chi, uint32_t* Clo,
                        int M, int N, int K2)
{
    constexpr int BN = 128, ST = 20;
    int smem = 2 * (2 * BM + 2 * BN) * ST * 4;
    auto kfn = gemm_bs<BM, BN, WY, WX, ACT, OMODE, ACCUM, ADDROW>;
    cudaFuncSetAttribute(kfn, cudaFuncAttributeMaxDynamicSharedMemorySize, smem);
    kfn<<<dim3(N / BN, M / BM), 256, smem>>>(Ah, Al, Bh, Bl, bias, ra, C, Chi, Clo, M, N, K2);
}

static void wsplit(const float* W, uint32_t* hi, uint32_t* lo, int K2, int N)
{
    int total = K2 * N;
    wsplit_k<<<(total + 255) / 256, 256>>>(W, hi, lo, K2, N);
}

extern "C" void kernel_launch(void* const* d_in, const int* in_sizes, int n_in,
                              void* d_out, int out_size)
{
    const float* state  = (const float*)d_in[0];
    const float* fc1_w  = (const float*)d_in[1];
    const float* fc1_b  = (const float*)d_in[2];
    const float* fc2_w  = (const float*)d_in[3];
    const float* fc2_b  = (const float*)d_in[4];
    const float* fc3_w  = (const float*)d_in[5];
    const float* fc3_b  = (const float*)d_in[6];
    const float* fc4_w  = (const float*)d_in[7];
    const float* fc4_b  = (const float*)d_in[8];
    const float* fc5_w  = (const float*)d_in[9];
    const float* fc5_b  = (const float*)d_in[10];
    const float* pre_w  = (const float*)d_in[11];
    const float* pre_b  = (const float*)d_in[12];
    const float* pos_w  = (const float*)d_in[13];
    const float* enc_w  = (const float*)d_in[14];
    const float* enc_b  = (const float*)d_in[15];
    const float* ln1_g  = (const float*)d_in[16];
    const float* ln1_b  = (const float*)d_in[17];
    const float* ln2_g  = (const float*)d_in[18];
    const float* ln2_b  = (const float*)d_in[19];
    const float* res_w1 = (const float*)d_in[20];
    const float* res_b1 = (const float*)d_in[21];
    const float* res_w2 = (const float*)d_in[22];
    const float* res_b2 = (const float*)d_in[23];
    const float* out_w  = (const float*)d_in[24];
    const float* out_b  = (const float*)d_in[25];
    float* out = (float*)d_out;

    uint32_t *wh, *wl, *ah1, *al1, *ah2, *al2;
    float *x, *qkv, *att;
    cudaGetSymbolAddress((void**)&wh,  g_wh);
    cudaGetSymbolAddress((void**)&wl,  g_wl);
    cudaGetSymbolAddress((void**)&ah1, g_ah1);
    cudaGetSymbolAddress((void**)&al1, g_al1);
    cudaGetSymbolAddress((void**)&ah2, g_ah2);
    cudaGetSymbolAddress((void**)&al2, g_al2);
    cudaGetSymbolAddress((void**)&x,   g_x);
    cudaGetSymbolAddress((void**)&qkv, g_qkv);
    cudaGetSymbolAddress((void**)&att, g_att);

    const int M = TOK;

    // ---- weight splits (once per launch; graph replays them, cheap) ----
    wsplit(fc1_w, wh + W1_OFF,   wl + W1_OFF,   2048, 4096);
    wsplit(fc2_w, wh + W2_OFF,   wl + W2_OFF,   2048, 2048);
    wsplit(fc3_w, wh + W3_OFF,   wl + W3_OFF,   1024, 1024);
    wsplit(fc4_w, wh + W4_OFF,   wl + W4_OFF,    512,  512);
    wsplit(fc5_w, wh + W5_OFF,   wl + W5_OFF,    256,  256);
    wsplit(pre_w, wh + WPRE_OFF, wl + WPRE_OFF,  128,  256);
    wsplit(enc_w, wh + WENC_OFF, wl + WENC_OFF, 1024,  768);   // [8*256][768]
    wsplit(res_w1, wh + WR1_OFF, wl + WR1_OFF,  1024, 1024);   // [8*256][1024]
    wsplit(res_w2, wh + WR2_OFF, wl + WR2_OFF,  4096,  256);   // [8*1024][256]
    wsplit(out_w,  wh + WOUT_OFF, wl + WOUT_OFF, 128,  128);

    // ---- input split ----
    asplit_k<<<(M * 2048 + 255) / 256, 256>>>(state, ah1, al1, M * 2048);

    // ---- MLP stack (split in -> split out; no fp32 intermediates) ----
    launch_gemm<128, 2, 4, 1, 1, false, false>(ah1, al1, wh + W1_OFF, wl + W1_OFF,
        fc1_b, nullptr, nullptr, ah2, al2, M, 4096, 2048);
    launch_gemm<128, 2, 4, 1, 1, false, false>(ah2, al2, wh + W2_OFF, wl + W2_OFF,
        fc2_b, nullptr, nullptr, ah1, al1, M, 2048, 2048);
    launch_gemm<128, 2, 4, 1, 1, false, false>(ah1, al1, wh + W3_OFF, wl + W3_OFF,
        fc3_b, nullptr, nullptr, ah2, al2, M, 1024, 1024);
    launch_gemm<128, 2, 4, 1, 1, false, false>(ah2, al2, wh + W4_OFF, wl + W4_OFF,
        fc4_b, nullptr, nullptr, ah1, al1, M, 512, 512);
    launch_gemm<64, 1, 8, 2, 1, false, false>(ah1, al1, wh + W5_OFF, wl + W5_OFF,
        fc5_b, nullptr, nullptr, ah2, al2, M, 256, 256);
    // pre projection + positional add -> fp32 x
    launch_gemm<64, 1, 8, 0, 0, false, true>(ah2, al2, wh + WPRE_OFF, wl + WPRE_OFF,
        pre_b, pos_w, x, nullptr, nullptr, M, 256, 128);

    // ---- transformer blocks ----
    for (int l = 0; l < NBLK; l++) {
        ln_k<false, false, true><<<TOK, 128>>>(x, nullptr, ln1_g + l * DD, ln1_b + l * DD,
                                               nullptr, ah1, al1);
        launch_gemm<128, 2, 4, 0, 0, false, false>(ah1, al1,
            wh + WENC_OFF + (size_t)l * 128 * 768, wl + WENC_OFF + (size_t)l * 128 * 768,
            enc_b + l * 3 * DD, nullptr, qkv, nullptr, nullptr, M, 768, 128);
        attn_k<<<dim3(SS / 128, HH, BB), 256>>>(qkv, att);
        ln_k<true, true, true><<<TOK, 128>>>(x, att, ln2_g + l * DD, ln2_b + l * DD,
                                             x, ah1, al1);
        launch_gemm<128, 2, 4, 3, 1, false, false>(ah1, al1,
            wh + WR1_OFF + (size_t)l * 128 * 1024, wl + WR1_OFF + (size_t)l * 128 * 1024,
            res_b1 + l * 4 * DD, nullptr, nullptr, ah2, al2, M, 1024, 128);
        launch_gemm<64, 1, 8, 0, 0, true, false>(ah2, al2,
            wh + WR2_OFF + (size_t)l * 512 * 256, wl + WR2_OFF + (size_t)l * 512 * 256,
            res_b2 + l * DD, nullptr, x, nullptr, nullptr, M, 256, 512);
    }

    // ---- output projection + global normalize ----
    asplit_k<<<(M * 128 + 255) / 256, 256>>>(x, ah1, al1, M * 128);
    launch_gemm<64, 1, 8, 0, 0, false, false>(ah1, al1, wh + WOUT_OFF, wl + WOUT_OFF,
        out_b, nullptr, out, nullptr, nullptr, M, 128, 128);

    int n = TOK * 128;
    zero_red_k<<<1, 1>>>();
    reduce_k<<<256, 256>>>(out, n);
    stats_k<<<1, 1>>>(n);
    norm_k<<<(n + 255) / 256, 256>>>(out, n);
}

// round 8
// speedup vs baseline: 3.5319x; 1.4338x over previous
#include <cuda_runtime.h>
#include <cuda_bf16.h>
#include <math.h>
#include <stdint.h>

// Problem dims
#define BB 8
#define SS 512
#define DD 256
#define HH 8
#define DHH 32
#define NBLK 8
#define TOK (BB*SS)          // 4096 tokens

// ---------------- device scratch ----------------
// weight split arena (u32 = bf16x2 pairs along K), layout [N][K2]  (K-pair contiguous)
#define W1_OFF   0u
#define W1_SZ    (2048u*4096u)
#define W2_OFF   (W1_OFF + W1_SZ)
#define W2_SZ    (2048u*2048u)
#define W3_OFF   (W2_OFF + W2_SZ)
#define W3_SZ    (1024u*1024u)
#define W4_OFF   (W3_OFF + W3_SZ)
#define W4_SZ    (512u*512u)
#define W5_OFF   (W4_OFF + W4_SZ)
#define W5_SZ    (256u*256u)
#define WPRE_OFF (W5_OFF + W5_SZ)
#define WPRE_SZ  (128u*256u)
#define WENC_OFF (WPRE_OFF + WPRE_SZ)
#define WENC_SZ  (1024u*768u)
#define WR1_OFF  (WENC_OFF + WENC_SZ)
#define WR1_SZ   (1024u*1024u)
#define WR2_OFF  (WR1_OFF + WR1_SZ)
#define WR2_SZ   (4096u*256u)
#define WOUT_OFF (WR2_OFF + WR2_SZ)
#define WOUT_SZ  (128u*128u)
#define WARENA   (WOUT_OFF + WOUT_SZ)

__device__ uint32_t g_wh[WARENA];
__device__ uint32_t g_wl[WARENA];

// activation split ping-pong arenas: [M][K2] u32, max 4096 x 2048
__device__ uint32_t g_ah1[4096u*2048u];
__device__ uint32_t g_al1[4096u*2048u];
__device__ uint32_t g_ah2[4096u*2048u];
__device__ uint32_t g_al2[4096u*2048u];

__device__ float g_x  [TOK * DD];
__device__ float g_qkv[TOK * 3 * DD];
__device__ float g_att[TOK * DD];
__device__ double g_red[2];
__device__ float g_stats[2];

// ---------------- bf16 split helpers ----------------
__device__ __forceinline__ void split_pair(float x, float y, uint32_t& hi, uint32_t& lo)
{
    __nv_bfloat16 hx = __float2bfloat16_rn(x);
    __nv_bfloat16 hy = __float2bfloat16_rn(y);
    float rx = x - __bfloat162float(hx);
    float ry = y - __bfloat162float(hy);
    __nv_bfloat162 h2; h2.x = hx; h2.y = hy;
    __nv_bfloat162 l2; l2.x = __float2bfloat16_rn(rx); l2.y = __float2bfloat16_rn(ry);
    hi = *reinterpret_cast<uint32_t*>(&h2);
    lo = *reinterpret_cast<uint32_t*>(&l2);
}

__device__ __forceinline__ void mma16816(float* c, const uint32_t* a, const uint32_t* b)
{
    asm volatile(
        "mma.sync.aligned.m16n8k16.row.col.f32.bf16.bf16.f32 "
        "{%0,%1,%2,%3},{%4,%5,%6,%7},{%8,%9},{%0,%1,%2,%3};"
        : "+f"(c[0]), "+f"(c[1]), "+f"(c[2]), "+f"(c[3])
        : "r"(a[0]), "r"(a[1]), "r"(a[2]), "r"(a[3]), "r"(b[0]), "r"(b[1]));
}

__device__ __forceinline__ void ldsm4(uint32_t* r, uint32_t addr)
{
    asm volatile("ldmatrix.sync.aligned.m8n8.x4.shared.b16 {%0,%1,%2,%3},[%4];"
                 : "=r"(r[0]), "=r"(r[1]), "=r"(r[2]), "=r"(r[3]) : "r"(addr));
}

__device__ __forceinline__ void cp16(uint32_t saddr, const void* g)
{
    asm volatile("cp.async.cg.shared.global [%0],[%1],16;" :: "r"(saddr), "l"(g));
}
__device__ __forceinline__ void cp_commit() { asm volatile("cp.async.commit_group;"); }
template<int N>
__device__ __forceinline__ void cp_wait() { asm volatile("cp.async.wait_group %0;" :: "n"(N)); }

// ---------------- split kernels ----------------
// weight transpose+split: fp32 [K][N] -> hi/lo u32 [N][K2]
__global__ void wsplit_t(const float* __restrict__ W, uint32_t* __restrict__ hi,
                         uint32_t* __restrict__ lo, int K2, int N)
{
    __shared__ uint32_t sh[32][33], sl[32][33];
    int kp0 = blockIdx.x * 32, n0 = blockIdx.y * 32;
    int tx = threadIdx.x, ty = threadIdx.y;   // (32,8)
#pragma unroll
    for (int i = ty; i < 32; i += 8) {
        int kp = kp0 + i;
        float f0 = W[(size_t)(2 * kp)     * N + n0 + tx];
        float f1 = W[(size_t)(2 * kp + 1) * N + n0 + tx];
        uint32_t h, l;
        split_pair(f0, f1, h, l);
        sh[i][tx] = h; sl[i][tx] = l;
    }
    __syncthreads();
#pragma unroll
    for (int j = ty; j < 32; j += 8) {
        hi[(size_t)(n0 + j) * K2 + kp0 + tx] = sh[tx][j];
        lo[(size_t)(n0 + j) * K2 + kp0 + tx] = sl[tx][j];
    }
}

// activation: fp32 row-major, pairs along K
__global__ void asplit_k(const float* __restrict__ A, uint32_t* __restrict__ hi,
                         uint32_t* __restrict__ lo, int total)
{
    int idx = blockIdx.x * blockDim.x + threadIdx.x;
    if (idx >= total) return;
    float2 v = reinterpret_cast<const float2*>(A)[idx];
    uint32_t h, l;
    split_pair(v.x, v.y, h, l);
    hi[idx] = h; lo[idx] = l;
}

// ---------------- tensor-core GEMM, bf16x3, cp.async 3-stage + ldmatrix ----------------
// A: hi/lo [M][K2], B: hi/lo [N][K2].  C = act(A@B + bias (+rowadd))
// OMODE: 0 = write fp32 C, 1 = write split Chi/Clo [M][N/2]
template<int BM, int BN, int WY, int WX, int ACT, int OMODE, bool ACCUM, bool ADDROW>
__global__ __launch_bounds__(256, 1)
void gemm_bs(const uint32_t* __restrict__ Ahg, const uint32_t* __restrict__ Alg,
             const uint32_t* __restrict__ Bhg, const uint32_t* __restrict__ Blg,
             const float* __restrict__ bias, const float* __restrict__ rowadd,
             float* __restrict__ C, uint32_t* __restrict__ Chi, uint32_t* __restrict__ Clo,
             int M, int N, int K2)
{
    constexpr int STAGES = 3;
    constexpr int KP = 16;               // K-pairs per stage (K=32)
    constexpr int ST = 20;               // row stride u32 (conflict-free, 80B)
    constexpr int WTM = BM / WY;
    constexpr int WTN = BN / WX;
    constexpr int MT = WTM / 16;
    constexpr int NT = WTN / 8;
    constexpr int AC = (BM * 4) / 256;   // cp16 ops/thread per A array
    constexpr int BC = (BN * 4) / 256;   // cp16 ops/thread per B array
    constexpr int SZ = (2 * BM + 2 * BN) * ST;  // u32 per stage
    static_assert(WY * WX == 8, "8 warps");
    static_assert(NT % 2 == 0, "NT even");

    extern __shared__ uint32_t sm[];
    uint32_t sbase;
    asm("{ .reg .u64 t; cvta.to.shared.u64 t, %1; cvt.u32.u64 %0, t; }"
        : "=r"(sbase) : "l"(sm));

    const int tid  = threadIdx.x;
    const int lane = tid & 31;
    const int warp = tid >> 5;
    const int wy = warp / WX, wx = warp % WX;
    const int bm = blockIdx.y * BM, bn = blockIdx.x * BN;
    const int g = lane >> 2, t4 = lane & 3;

    // ldmatrix per-lane offsets (u32 units, within a stage buffer)
    const uint32_t aoffA = (uint32_t)((wy * WTM + (lane & 15)) * ST + (lane >> 4) * 4);
    const int q = lane >> 3;
    const uint32_t boffB = (uint32_t)((wx * WTN + (q >> 1) * 8 + (lane & 7)) * ST + (q & 1) * 4);

    float acc[MT][NT][4];
#pragma unroll
    for (int i = 0; i < MT; i++)
#pragma unroll
        for (int j = 0; j < NT; j++)
#pragma unroll
            for (int r = 0; r < 4; r++) acc[i][j][r] = 0.f;

    const int NS = K2 / KP;

    auto issue = [&](int s) {
        const int buf = s % STAGES;
        const uint32_t sb = sbase + (uint32_t)buf * (SZ * 4);
        const int k2 = s * KP;
#pragma unroll
        for (int it = 0; it < AC; it++) {
            int idx = tid + it * 256;
            int r = idx >> 2, c = idx & 3;
            size_t off = (size_t)(bm + r) * K2 + k2 + c * 4;
            uint32_t so = (uint32_t)(r * ST + c * 4) * 4;
            cp16(sb + so,                 Ahg + off);
            cp16(sb + BM * ST * 4 + so,   Alg + off);
        }
#pragma unroll
        for (int it = 0; it < BC; it++) {
            int idx = tid + it * 256;
            int r = idx >> 2, c = idx & 3;
            size_t off = (size_t)(bn + r) * K2 + k2 + c * 4;
            uint32_t so = (uint32_t)(r * ST + c * 4) * 4;
            cp16(sb + 2 * BM * ST * 4 + so,            Bhg + off);
            cp16(sb + (2 * BM + BN) * ST * 4 + so,     Blg + off);
        }
        cp_commit();
    };

    auto compute = [&](int buf) {
        const uint32_t s0 = sbase + (uint32_t)buf * (SZ * 4);
        const uint32_t aH = s0;
        const uint32_t aL = s0 + BM * ST * 4;
        const uint32_t bH = s0 + 2 * BM * ST * 4;
        const uint32_t bL = s0 + (2 * BM + BN) * ST * 4;
#pragma unroll
        for (int kk = 0; kk < 2; kk++) {
            const uint32_t kb = (uint32_t)(kk * 8) * 4;
            uint32_t ah[MT][4], al[MT][4], bh[NT][2], bl[NT][2];
#pragma unroll
            for (int mt = 0; mt < MT; mt++) {
                uint32_t off = (aoffA + mt * 16 * ST) * 4 + kb;
                ldsm4(ah[mt], aH + off);
                ldsm4(al[mt], aL + off);
            }
#pragma unroll
            for (int p = 0; p < NT / 2; p++) {
                uint32_t off = (boffB + p * 16 * ST) * 4 + kb;
                uint32_t t[4];
                ldsm4(t, bH + off);
                bh[2*p][0] = t[0]; bh[2*p][1] = t[1];
                bh[2*p+1][0] = t[2]; bh[2*p+1][1] = t[3];
                ldsm4(t, bL + off);
                bl[2*p][0] = t[0]; bl[2*p][1] = t[1];
                bl[2*p+1][0] = t[2]; bl[2*p+1][1] = t[3];
            }
#pragma unroll
            for (int mt = 0; mt < MT; mt++)
#pragma unroll
                for (int nt = 0; nt < NT; nt++) {
                    mma16816(acc[mt][nt], ah[mt], bh[nt]);  // hi*hi
                    mma16816(acc[mt][nt], ah[mt], bl[nt]);  // hi*lo
                    mma16816(acc[mt][nt], al[mt], bh[nt]);  // lo*hi
                }
        }
    };

    issue(0);
    issue(1);
    for (int s = 0; s < NS; s++) {
        cp_wait<STAGES - 2>();
        __syncthreads();
        if (s + STAGES - 1 < NS) issue(s + STAGES - 1);
        else cp_commit();
        compute(s % STAGES);
    }

    // --- epilogue: pairs (col, col+1) ---
    auto epi = [&](int row, int col, float v0, float v1) {
        v0 += bias[col]; v1 += bias[col + 1];
        if (ADDROW) {
            const float* ra = rowadd + (size_t)(row % SS) * N + col;
            v0 += ra[0]; v1 += ra[1];
        }
        if (ACT == 1) { v0 = fmaxf(v0, 0.f); v1 = fmaxf(v1, 0.f); }
        else if (ACT == 2) { v0 = tanhf(v0); v1 = tanhf(v1); }
        else if (ACT == 3) {
            v0 = 0.5f * v0 * (1.f + erff(v0 * 0.70710678118654752f));
            v1 = 0.5f * v1 * (1.f + erff(v1 * 0.70710678118654752f));
        }
        if (OMODE == 0) {
            float* cp = C + (size_t)row * N + col;
            if (ACCUM) { cp[0] += v0; cp[1] += v1; }
            else       { float2 o; o.x = v0; o.y = v1; *reinterpret_cast<float2*>(cp) = o; }
        } else {
            uint32_t h, l;
            split_pair(v0, v1, h, l);
            size_t pi = (size_t)row * (N / 2) + col / 2;
            Chi[pi] = h; Clo[pi] = l;
        }
    };

#pragma unroll
    for (int mt = 0; mt < MT; mt++) {
        int r0 = bm + wy * WTM + mt * 16 + g;
#pragma unroll
        for (int nt = 0; nt < NT; nt++) {
            int c = bn + wx * WTN + nt * 8 + t4 * 2;
            epi(r0,     c, acc[mt][nt][0], acc[mt][nt][1]);
            epi(r0 + 8, c, acc[mt][nt][2], acc[mt][nt][3]);
        }
    }
}

// ---------------- LayerNorm over D=256, 128 threads x float2 ----------------
template<bool ADD, bool WF, bool WS>
__global__ void ln_k(const float* __restrict__ x, const float* __restrict__ add,
                     const float* __restrict__ g, const float* __restrict__ b,
                     float* __restrict__ outf, uint32_t* __restrict__ ohi,
                     uint32_t* __restrict__ olo)
{
    int t = blockIdx.x;
    int tid = threadIdx.x;    // 128
    float2 v = reinterpret_cast<const float2*>(x + (size_t)t * DD)[tid];
    if (ADD) {
        float2 a2 = reinterpret_cast<const float2*>(add + (size_t)t * DD)[tid];
        v.x += a2.x; v.y += a2.y;
    }
    float s = v.x + v.y, q = v.x * v.x + v.y * v.y;
#pragma unroll
    for (int o = 16; o > 0; o >>= 1) {
        s += __shfl_xor_sync(0xffffffffu, s, o);
        q += __shfl_xor_sync(0xffffffffu, q, o);
    }
    __shared__ float ws[4], wq[4];
    int w = tid >> 5, lane = tid & 31;
    if (lane == 0) { ws[w] = s; wq[w] = q; }
    __syncthreads();
    float ts = ws[0] + ws[1] + ws[2] + ws[3];
    float tq = wq[0] + wq[1] + wq[2] + wq[3];
    float mean = ts * (1.f / DD);
    float var  = tq * (1.f / DD) - mean * mean;
    float r = rsqrtf(var + 1e-5f);
    float2 gg = reinterpret_cast<const float2*>(g)[tid];
    float2 bb = reinterpret_cast<const float2*>(b)[tid];
    float y0 = (v.x - mean) * r * gg.x + bb.x;
    float y1 = (v.y - mean) * r * gg.y + bb.y;
    if (WF) {
        float2 o; o.x = y0; o.y = y1;
        reinterpret_cast<float2*>(outf + (size_t)t * DD)[tid] = o;
    }
    if (WS) {
        uint32_t h, l;
        split_pair(y0, y1, h, l);
        ohi[(size_t)t * (DD / 2) + tid] = h;
        olo[(size_t)t * (DD / 2) + tid] = l;
    }
}

// ---------------- flash-style causal attention ----------------
// grid (S/128, H, B), 256 threads: 2 threads per q-row (half = tid&1, 32 k each per 64-ktile)
__global__ __launch_bounds__(256, 2)
void attn_k(const float* __restrict__ qkv, float* __restrict__ att)
{
    constexpr int KT = 64;
    constexpr int VST = 36;   // smem row stride (floats)
    __shared__ float Ks[KT * VST];
    __shared__ float Vs[KT * VST];

    const int qt = blockIdx.x, h = blockIdx.y, b = blockIdx.z;
    const int tid = threadIdx.x;
    const int r = tid >> 1, half = tid & 1;
    const int qg = qt * 128 + r;

    const float* base = qkv + (size_t)(b * SS) * (3 * DD);
    const float scale = rsqrtf((float)DHH);

    float qreg[DHH];
    {
        const float4* qp = reinterpret_cast<const float4*>(base + (size_t)qg * (3 * DD) + h * DHH);
#pragma unroll
        for (int i = 0; i < 8; i++) {
            float4 f = qp[i];
            qreg[i*4+0] = f.x * scale; qreg[i*4+1] = f.y * scale;
            qreg[i*4+2] = f.z * scale; qreg[i*4+3] = f.w * scale;
        }
    }

    float m = -1e30f, lsum = 0.f;
    float o[DHH];
#pragma unroll
    for (int d = 0; d < DHH; d++) o[d] = 0.f;

    const int ntiles = (qt + 1) * 2;
    for (int kt = 0; kt < ntiles; kt++) {
#pragma unroll
        for (int it = 0; it < 2; it++) {
            int idx = tid + it * 256;
            int rr = idx >> 3, c = idx & 7;
            int k = kt * KT + rr;
            const float4* kp = reinterpret_cast<const float4*>(base + (size_t)k * (3 * DD) + DD + h * DHH);
            const float4* vp = reinterpret_cast<const float4*>(base + (size_t)k * (3 * DD) + 2 * DD + h * DHH);
            *reinterpret_cast<float4*>(&Ks[rr * VST + c * 4]) = kp[c];
            *reinterpret_cast<float4*>(&Vs[rr * VST + c * 4]) = vp[c];
        }
        __syncthreads();

        const int kbase = kt * KT + half * 32;
        if (kbase <= qg) {
            float p[32];
            float smax = -1e30f;
#pragma unroll 4
            for (int kk = 0; kk < 32; kk++) {
                const float* kr = &Ks[(half * 32 + kk) * VST];
                float dot = 0.f;
#pragma unroll
                for (int d = 0; d < DHH; d++) dot = fmaf(qreg[d], kr[d], dot);
                if (kbase + kk > qg) dot = -1e30f;
                p[kk] = dot;
                smax = fmaxf(smax, dot);
            }
            float newm = fmaxf(m, smax);
            float f = __expf(m - newm);
            float ls = 0.f;
#pragma unroll
            for (int kk = 0; kk < 32; kk++) {
                p[kk] = __expf(p[kk] - newm);
                ls += p[kk];
            }
            lsum = lsum * f + ls;
#pragma unroll
            for (int d = 0; d < DHH; d++) o[d] *= f;
#pragma unroll 4
            for (int kk = 0; kk < 32; kk++) {
                const float* vr = &Vs[(half * 32 + kk) * VST];
                float pk = p[kk];
#pragma unroll
                for (int d = 0; d < DHH; d++) o[d] = fmaf(pk, vr[d], o[d]);
            }
            m = newm;
        }
        __syncthreads();
    }

    float om = __shfl_xor_sync(0xffffffffu, m, 1);
    float nm = fmaxf(m, om);
    float fs = __expf(m - nm);
    float lS = lsum * fs;
    float lT = lS + __shfl_xor_sync(0xffffffffu, lS, 1);
    float inv = 1.f / lT;
    float* op = att + (size_t)(b * SS + qg) * DD + h * DHH;
#pragma unroll
    for (int d = 0; d < DHH; d++) {
        float oS = o[d] * fs;
        float oT = oS + __shfl_xor_sync(0xffffffffu, oS, 1);
        if (half == 0) op[d] = oT * inv;
    }
}

// ---------------- global normalize (mean / std ddof=1, + 1e-10) ----------------
__global__ void zero_red_k() { g_red[0] = 0.0; g_red[1] = 0.0; }

__global__ void reduce_k(const float* __restrict__ x, int n)
{
    double s = 0.0, q = 0.0;
    for (int i = blockIdx.x * blockDim.x + threadIdx.x; i < n; i += gridDim.x * blockDim.x) {
        double v = (double)x[i];
        s += v; q += v * v;
    }
#pragma unroll
    for (int o = 16; o > 0; o >>= 1) {
        s += __shfl_xor_sync(0xffffffffu, s, o);
        q += __shfl_xor_sync(0xffffffffu, q, o);
    }
    __shared__ double ws[8], wq[8];
    int w = threadIdx.x >> 5, lane = threadIdx.x & 31;
    if (lane == 0) { ws[w] = s; wq[w] = q; }
    __syncthreads();
    if (threadIdx.x == 0) {
        double ts = 0.0, tq = 0.0;
        for (int i = 0; i < (int)(blockDim.x / 32); i++) { ts += ws[i]; tq += wq[i]; }
        atomicAdd(&g_red[0], ts);
        atomicAdd(&g_red[1], tq);
    }
}

__global__ void stats_k(int n)
{
    double mean = g_red[0] / n;
    double var = (g_red[1] - (double)n * mean * mean) / (double)(n - 1);
    g_stats[0] = (float)mean;
    g_stats[1] = (float)(1.0 / sqrt(var));
}

__global__ void norm_k(float* __restrict__ x, int n)
{
    int i = blockIdx.x * blockDim.x + threadIdx.x;
    if (i < n) x[i] = (x[i] - g_stats[0]) * g_stats[1] + 1e-10f;
}

// ---------------- host-side launch helpers ----------------
template<int BM, int WY, int WX, int ACT, int OMODE, bool ACCUM, bool ADDROW>
static void launch_gemm(const uint32_t* Ah, const uint32_t* Al,
                        const uint32_t* Bh, const uint32_t* Bl,
                        const float* bias, const float* ra,
                        float* C, uint32_t* Chi, uint32_t* Clo,
                        int M, int N, int K2)
{
    constexpr int BN = 128, ST = 20;
    int smem = 3 * (2 * BM + 2 * BN) * ST * 4;
    auto kfn = gemm_bs<BM, BN, WY, WX, ACT, OMODE, ACCUM, ADDROW>;
    cudaFuncSetAttribute(kfn, cudaFuncAttributeMaxDynamicSharedMemorySize, smem);
    kfn<<<dim3(N / BN, M / BM), 256, smem>>>(Ah, Al, Bh, Bl, bias, ra, C, Chi, Clo, M, N, K2);
}

static void wsplit(const float* W, uint32_t* hi, uint32_t* lo, int K2, int N)
{
    wsplit_t<<<dim3(K2 / 32, N / 32), dim3(32, 8)>>>(W, hi, lo, K2, N);
}

extern "C" void kernel_launch(void* const* d_in, const int* in_sizes, int n_in,
                              void* d_out, int out_size)
{
    const float* state  = (const float*)d_in[0];
    const float* fc1_w  = (const float*)d_in[1];
    const float* fc1_b  = (const float*)d_in[2];
    const float* fc2_w  = (const float*)d_in[3];
    const float* fc2_b  = (const float*)d_in[4];
    const float* fc3_w  = (const float*)d_in[5];
    const float* fc3_b  = (const float*)d_in[6];
    const float* fc4_w  = (const float*)d_in[7];
    const float* fc4_b  = (const float*)d_in[8];
    const float* fc5_w  = (const float*)d_in[9];
    const float* fc5_b  = (const float*)d_in[10];
    const float* pre_w  = (const float*)d_in[11];
    const float* pre_b  = (const float*)d_in[12];
    const float* pos_w  = (const float*)d_in[13];
    const float* enc_w  = (const float*)d_in[14];
    const float* enc_b  = (const float*)d_in[15];
    const float* ln1_g  = (const float*)d_in[16];
    const float* ln1_b  = (const float*)d_in[17];
    const float* ln2_g  = (const float*)d_in[18];
    const float* ln2_b  = (const float*)d_in[19];
    const float* res_w1 = (const float*)d_in[20];
    const float* res_b1 = (const float*)d_in[21];
    const float* res_w2 = (const float*)d_in[22];
    const float* res_b2 = (const float*)d_in[23];
    const float* out_w  = (const float*)d_in[24];
    const float* out_b  = (const float*)d_in[25];
    float* out = (float*)d_out;

    uint32_t *wh, *wl, *ah1, *al1, *ah2, *al2;
    float *x, *qkv, *att;
    cudaGetSymbolAddress((void**)&wh,  g_wh);
    cudaGetSymbolAddress((void**)&wl,  g_wl);
    cudaGetSymbolAddress((void**)&ah1, g_ah1);
    cudaGetSymbolAddress((void**)&al1, g_al1);
    cudaGetSymbolAddress((void**)&ah2, g_ah2);
    cudaGetSymbolAddress((void**)&al2, g_al2);
    cudaGetSymbolAddress((void**)&x,   g_x);
    cudaGetSymbolAddress((void**)&qkv, g_qkv);
    cudaGetSymbolAddress((void**)&att, g_att);

    const int M = TOK;

    // ---- weight transpose+splits -> [N][K2] ----
    wsplit(fc1_w, wh + W1_OFF,   wl + W1_OFF,   2048, 4096);
    wsplit(fc2_w, wh + W2_OFF,   wl + W2_OFF,   2048, 2048);
    wsplit(fc3_w, wh + W3_OFF,   wl + W3_OFF,   1024, 1024);
    wsplit(fc4_w, wh + W4_OFF,   wl + W4_OFF,    512,  512);
    wsplit(fc5_w, wh + W5_OFF,   wl + W5_OFF,    256,  256);
    wsplit(pre_w, wh + WPRE_OFF, wl + WPRE_OFF,  128,  256);
    for (int l = 0; l < NBLK; l++) {
        wsplit(enc_w  + (size_t)l * 256 * 768,  wh + WENC_OFF + (size_t)l * 98304,
               wl + WENC_OFF + (size_t)l * 98304,  128,  768);
        wsplit(res_w1 + (size_t)l * 256 * 1024, wh + WR1_OFF + (size_t)l * 131072,
               wl + WR1_OFF + (size_t)l * 131072, 128, 1024);
        wsplit(res_w2 + (size_t)l * 1024 * 256, wh + WR2_OFF + (size_t)l * 131072,
               wl + WR2_OFF + (size_t)l * 131072, 512,  256);
    }
    wsplit(out_w, wh + WOUT_OFF, wl + WOUT_OFF, 128, 128);

    // ---- input split ----
    asplit_k<<<(M * 2048 + 255) / 256, 256>>>(state, ah1, al1, M * 2048);

    // ---- MLP stack (split in -> split out) ----
    launch_gemm<128, 2, 4, 1, 1, false, false>(ah1, al1, wh + W1_OFF, wl + W1_OFF,
        fc1_b, nullptr, nullptr, ah2, al2, M, 4096, 2048);
    launch_gemm<128, 2, 4, 1, 1, false, false>(ah2, al2, wh + W2_OFF, wl + W2_OFF,
        fc2_b, nullptr, nullptr, ah1, al1, M, 2048, 2048);
    launch_gemm<128, 2, 4, 1, 1, false, false>(ah1, al1, wh + W3_OFF, wl + W3_OFF,
        fc3_b, nullptr, nullptr, ah2, al2, M, 1024, 1024);
    launch_gemm<128, 2, 4, 1, 1, false, false>(ah2, al2, wh + W4_OFF, wl + W4_OFF,
        fc4_b, nullptr, nullptr, ah1, al1, M, 512, 512);
    launch_gemm<64, 1, 8, 2, 1, false, false>(ah1, al1, wh + W5_OFF, wl + W5_OFF,
        fc5_b, nullptr, nullptr, ah2, al2, M, 256, 256);
    launch_gemm<64, 1, 8, 0, 0, false, true>(ah2, al2, wh + WPRE_OFF, wl + WPRE_OFF,
        pre_b, pos_w, x, nullptr, nullptr, M, 256, 128);

    // ---- transformer blocks ----
    for (int l = 0; l < NBLK; l++) {
        ln_k<false, false, true><<<TOK, 128>>>(x, nullptr, ln1_g + l * DD, ln1_b + l * DD,
                                               nullptr, ah1, al1);
        launch_gemm<128, 2, 4, 0, 0, false, false>(ah1, al1,
            wh + WENC_OFF + (size_t)l * 98304, wl + WENC_OFF + (size_t)l * 98304,
            enc_b + l * 3 * DD, nullptr, qkv, nullptr, nullptr, M, 768, 128);
        attn_k<<<dim3(SS / 128, HH, BB), 256>>>(qkv, att);
        ln_k<true, true, true><<<TOK, 128>>>(x, att, ln2_g + l * DD, ln2_b + l * DD,
                                             x, ah1, al1);
        launch_gemm<128, 2, 4, 3, 1, false, false>(ah1, al1,
            wh + WR1_OFF + (size_t)l * 131072, wl + WR1_OFF + (size_t)l * 131072,
            res_b1 + l * 4 * DD, nullptr, nullptr, ah2, al2, M, 1024, 128);
        launch_gemm<64, 1, 8, 0, 0, true, false>(ah2, al2,
            wh + WR2_OFF + (size_t)l * 131072, wl + WR2_OFF + (size_t)l * 131072,
            res_b2 + l * DD, nullptr, x, nullptr, nullptr, M, 256, 512);
    }

    // ---- output projection + global normalize ----
    asplit_k<<<(M * 128 + 255) / 256, 256>>>(x, ah1, al1, M * 128);
    launch_gemm<64, 1, 8, 0, 0, false, false>(ah1, al1, wh + WOUT_OFF, wl + WOUT_OFF,
        out_b, nullptr, out, nullptr, nullptr, M, 128, 128);

    int n = TOK * 128;
    zero_red_k<<<1, 1>>>();
    reduce_k<<<256, 256>>>(out, n);
    stats_k<<<1, 1>>>(n);
    norm_k<<<(n + 255) / 256, 256>>>(out, n);
}

// round 10
// speedup vs baseline: 3.7468x; 1.0608x over previous
#include <cuda_runtime.h>
#include <cuda_bf16.h>
#include <math.h>
#include <stdint.h>

// Problem dims
#define BB 8
#define SS 512
#define DD 256
#define HH 8
#define DHH 32
#define NBLK 8
#define TOK (BB*SS)          // 4096 tokens

// ---------------- device scratch ----------------
// weight split arena (u32 = bf16x2 pairs along K), layout [N][K2]  (K-pair contiguous)
#define W1_OFF   0u
#define W1_SZ    (2048u*4096u)
#define W2_OFF   (W1_OFF + W1_SZ)
#define W2_SZ    (2048u*2048u)
#define W3_OFF   (W2_OFF + W2_SZ)
#define W3_SZ    (1024u*1024u)
#define W4_OFF   (W3_OFF + W3_SZ)
#define W4_SZ    (512u*512u)
#define W5_OFF   (W4_OFF + W4_SZ)
#define W5_SZ    (256u*256u)
#define WPRE_OFF (W5_OFF + W5_SZ)
#define WPRE_SZ  (128u*256u)
#define WENC_OFF (WPRE_OFF + WPRE_SZ)
#define WENC_SZ  (1024u*768u)
#define WR1_OFF  (WENC_OFF + WENC_SZ)
#define WR1_SZ   (1024u*1024u)
#define WR2_OFF  (WR1_OFF + WR1_SZ)
#define WR2_SZ   (4096u*256u)
#define WOUT_OFF (WR2_OFF + WR2_SZ)
#define WOUT_SZ  (128u*128u)
#define WARENA   (WOUT_OFF + WOUT_SZ)

__device__ uint32_t g_wh[WARENA];
__device__ uint32_t g_wl[WARENA];

// activation split ping-pong arenas: [M][K2] u32, max 4096 x 2048
__device__ uint32_t g_ah1[4096u*2048u];
__device__ uint32_t g_al1[4096u*2048u];
__device__ uint32_t g_ah2[4096u*2048u];
__device__ uint32_t g_al2[4096u*2048u];

__device__ float g_x  [TOK * DD];
__device__ float g_qkv[TOK * 3 * DD];
__device__ float g_att[TOK * DD];
__device__ double g_red[2];
__device__ float g_stats[2];

// ---------------- bf16 split helpers ----------------
__device__ __forceinline__ void split_pair(float x, float y, uint32_t& hi, uint32_t& lo)
{
    __nv_bfloat16 hx = __float2bfloat16_rn(x);
    __nv_bfloat16 hy = __float2bfloat16_rn(y);
    float rx = x - __bfloat162float(hx);
    float ry = y - __bfloat162float(hy);
    __nv_bfloat162 h2; h2.x = hx; h2.y = hy;
    __nv_bfloat162 l2; l2.x = __float2bfloat16_rn(rx); l2.y = __float2bfloat16_rn(ry);
    hi = *reinterpret_cast<uint32_t*>(&h2);
    lo = *reinterpret_cast<uint32_t*>(&l2);
}

__device__ __forceinline__ void mma16816(float* c, const uint32_t* a, const uint32_t* b)
{
    asm volatile(
        "mma.sync.aligned.m16n8k16.row.col.f32.bf16.bf16.f32 "
        "{%0,%1,%2,%3},{%4,%5,%6,%7},{%8,%9},{%0,%1,%2,%3};"
        : "+f"(c[0]), "+f"(c[1]), "+f"(c[2]), "+f"(c[3])
        : "r"(a[0]), "r"(a[1]), "r"(a[2]), "r"(a[3]), "r"(b[0]), "r"(b[1]));
}

__device__ __forceinline__ void ldsm4(uint32_t* r, uint32_t addr)
{
    asm volatile("ldmatrix.sync.aligned.m8n8.x4.shared.b16 {%0,%1,%2,%3},[%4];"
                 : "=r"(r[0]), "=r"(r[1]), "=r"(r[2]), "=r"(r[3]) : "r"(addr));
}

__device__ __forceinline__ void cp16(uint32_t saddr, const void* g)
{
    asm volatile("cp.async.cg.shared.global [%0],[%1],16;" :: "r"(saddr), "l"(g));
}
__device__ __forceinline__ void cp_commit() { asm volatile("cp.async.commit_group;"); }
template<int N>
__device__ __forceinline__ void cp_wait() { asm volatile("cp.async.wait_group %0;" :: "n"(N)); }

// ---------------- split kernels ----------------
// weight transpose+split: fp32 [K][N] -> hi/lo u32 [N][K2], batched over blockIdx.z layers
__global__ void wsplit_b(const float* __restrict__ W0, uint32_t* __restrict__ hi0,
                         uint32_t* __restrict__ lo0, int K2, int N,
                         size_t wstride, size_t ostride)
{
    const float* W = W0 + (size_t)blockIdx.z * wstride;
    uint32_t* hi = hi0 + (size_t)blockIdx.z * ostride;
    uint32_t* lo = lo0 + (size_t)blockIdx.z * ostride;
    __shared__ uint32_t sh[32][33], sl[32][33];
    int kp0 = blockIdx.x * 32, n0 = blockIdx.y * 32;
    int tx = threadIdx.x, ty = threadIdx.y;   // (32,8)
#pragma unroll
    for (int i = ty; i < 32; i += 8) {
        int kp = kp0 + i;
        float f0 = W[(size_t)(2 * kp)     * N + n0 + tx];
        float f1 = W[(size_t)(2 * kp + 1) * N + n0 + tx];
        uint32_t h, l;
        split_pair(f0, f1, h, l);
        sh[i][tx] = h; sl[i][tx] = l;
    }
    __syncthreads();
#pragma unroll
    for (int j = ty; j < 32; j += 8) {
        hi[(size_t)(n0 + j) * K2 + kp0 + tx] = sh[tx][j];
        lo[(size_t)(n0 + j) * K2 + kp0 + tx] = sl[tx][j];
    }
}

// activation: fp32 row-major, pairs along K
__global__ void asplit_k(const float* __restrict__ A, uint32_t* __restrict__ hi,
                         uint32_t* __restrict__ lo, int total)
{
    int idx = blockIdx.x * blockDim.x + threadIdx.x;
    if (idx >= total) return;
    float2 v = reinterpret_cast<const float2*>(A)[idx];
    uint32_t h, l;
    split_pair(v.x, v.y, h, l);
    hi[idx] = h; lo[idx] = l;
}

// ---------------- tensor-core GEMM, bf16x3, cp.async 2-stage + ldmatrix, 2 CTA/SM ----------------
// A: hi/lo [M][K2], B: hi/lo [N][K2].  C = act(A@B + bias (+rowadd))
// OMODE: 0 = write fp32 C, 1 = write split Chi/Clo [M][N/2]
template<int BM, int BN, int WY, int WX, int ACT, int OMODE, bool ACCUM, bool ADDROW>
__global__ __launch_bounds__(256, 2)
void gemm_bs(const uint32_t* __restrict__ Ahg, const uint32_t* __restrict__ Alg,
             const uint32_t* __restrict__ Bhg, const uint32_t* __restrict__ Blg,
             const float* __restrict__ bias, const float* __restrict__ rowadd,
             float* __restrict__ C, uint32_t* __restrict__ Chi, uint32_t* __restrict__ Clo,
             int M, int N, int K2)
{
    constexpr int KP = 16;               // K-pairs per stage (K=32)
    constexpr int ST = 20;               // row stride u32 (conflict-free, 80B)
    constexpr int WTM = BM / WY;
    constexpr int WTN = BN / WX;
    constexpr int MT = WTM / 16;
    constexpr int NT = WTN / 8;
    constexpr int AC = (BM * 4) / 256;   // cp16 ops/thread per A array
    constexpr int BC = (BN * 4) / 256;   // cp16 ops/thread per B array
    constexpr int SZ = (2 * BM + 2 * BN) * ST;  // u32 per stage
    static_assert(WY * WX == 8, "8 warps");
    static_assert(NT % 2 == 0, "NT even");

    extern __shared__ uint32_t sm[];
    uint32_t sbase;
    asm("{ .reg .u64 t; cvta.to.shared.u64 t, %1; cvt.u32.u64 %0, t; }"
        : "=r"(sbase) : "l"(sm));

    const int tid  = threadIdx.x;
    const int lane = tid & 31;
    const int warp = tid >> 5;
    const int wy = warp / WX, wx = warp % WX;
    const int bm = blockIdx.y * BM, bn = blockIdx.x * BN;
    const int g = lane >> 2, t4 = lane & 3;

    // ldmatrix per-lane offsets (u32 units, within a stage buffer)
    const uint32_t aoffA = (uint32_t)((wy * WTM + (lane & 15)) * ST + (lane >> 4) * 4);
    const int q = lane >> 3;
    const uint32_t boffB = (uint32_t)((wx * WTN + (q >> 1) * 8 + (lane & 7)) * ST + (q & 1) * 4);

    float acc[MT][NT][4];
#pragma unroll
    for (int i = 0; i < MT; i++)
#pragma unroll
        for (int j = 0; j < NT; j++)
#pragma unroll
            for (int r = 0; r < 4; r++) acc[i][j][r] = 0.f;

    const int NS = K2 / KP;

    auto issue = [&](int s) {
        const int buf = s & 1;
        const uint32_t sb = sbase + (uint32_t)buf * (SZ * 4);
        const int k2 = s * KP;
#pragma unroll
        for (int it = 0; it < AC; it++) {
            int idx = tid + it * 256;
            int r = idx >> 2, c = idx & 3;
            size_t off = (size_t)(bm + r) * K2 + k2 + c * 4;
            uint32_t so = (uint32_t)(r * ST + c * 4) * 4;
            cp16(sb + so,                 Ahg + off);
            cp16(sb + BM * ST * 4 + so,   Alg + off);
        }
#pragma unroll
        for (int it = 0; it < BC; it++) {
            int idx = tid + it * 256;
            int r = idx >> 2, c = idx & 3;
            size_t off = (size_t)(bn + r) * K2 + k2 + c * 4;
            uint32_t so = (uint32_t)(r * ST + c * 4) * 4;
            cp16(sb + 2 * BM * ST * 4 + so,            Bhg + off);
            cp16(sb + (2 * BM + BN) * ST * 4 + so,     Blg + off);
        }
        cp_commit();
    };

    auto compute = [&](int buf) {
        const uint32_t s0 = sbase + (uint32_t)buf * (SZ * 4);
        const uint32_t aH = s0;
        const uint32_t aL = s0 + BM * ST * 4;
        const uint32_t bH = s0 + 2 * BM * ST * 4;
        const uint32_t bL = s0 + (2 * BM + BN) * ST * 4;
#pragma unroll
        for (int kk = 0; kk < 2; kk++) {
            const uint32_t kb = (uint32_t)(kk * 8) * 4;
            uint32_t ah[MT][4], al[MT][4], bh[NT][2], bl[NT][2];
#pragma unroll
            for (int mt = 0; mt < MT; mt++) {
                uint32_t off = (aoffA + mt * 16 * ST) * 4 + kb;
                ldsm4(ah[mt], aH + off);
                ldsm4(al[mt], aL + off);
            }
#pragma unroll
            for (int p = 0; p < NT / 2; p++) {
                uint32_t off = (boffB + p * 16 * ST) * 4 + kb;
                uint32_t t[4];
                ldsm4(t, bH + off);
                bh[2*p][0] = t[0]; bh[2*p][1] = t[1];
                bh[2*p+1][0] = t[2]; bh[2*p+1][1] = t[3];
                ldsm4(t, bL + off);
                bl[2*p][0] = t[0]; bl[2*p][1] = t[1];
                bl[2*p+1][0] = t[2]; bl[2*p+1][1] = t[3];
            }
#pragma unroll
            for (int mt = 0; mt < MT; mt++)
#pragma unroll
                for (int nt = 0; nt < NT; nt++) {
                    mma16816(acc[mt][nt], ah[mt], bh[nt]);  // hi*hi
                    mma16816(acc[mt][nt], ah[mt], bl[nt]);  // hi*lo
                    mma16816(acc[mt][nt], al[mt], bh[nt]);  // lo*hi
                }
        }
    };

    issue(0);
    issue(1);
    for (int s = 0; s < NS; s++) {
        if (s + 1 < NS) { cp_wait<1>(); } else { cp_wait<0>(); }
        __syncthreads();
        compute(s & 1);
        __syncthreads();
        if (s + 2 < NS) issue(s + 2);
    }

    // --- epilogue: pairs (col, col+1) ---
    auto epi = [&](int row, int col, float v0, float v1) {
        v0 += bias[col]; v1 += bias[col + 1];
        if (ADDROW) {
            const float* ra = rowadd + (size_t)(row % SS) * N + col;
            v0 += ra[0]; v1 += ra[1];
        }
        if (ACT == 1) { v0 = fmaxf(v0, 0.f); v1 = fmaxf(v1, 0.f); }
        else if (ACT == 2) { v0 = tanhf(v0); v1 = tanhf(v1); }
        else if (ACT == 3) {
            v0 = 0.5f * v0 * (1.f + erff(v0 * 0.70710678118654752f));
            v1 = 0.5f * v1 * (1.f + erff(v1 * 0.70710678118654752f));
        }
        if (OMODE == 0) {
            float* cp = C + (size_t)row * N + col;
            if (ACCUM) { cp[0] += v0; cp[1] += v1; }
            else       { float2 o; o.x = v0; o.y = v1; *reinterpret_cast<float2*>(cp) = o; }
        } else {
            uint32_t h, l;
            split_pair(v0, v1, h, l);
            size_t pi = (size_t)row * (N / 2) + col / 2;
            Chi[pi] = h; Clo[pi] = l;
        }
    };

#pragma unroll
    for (int mt = 0; mt < MT; mt++) {
        int r0 = bm + wy * WTM + mt * 16 + g;
#pragma unroll
        for (int nt = 0; nt < NT; nt++) {
            int c = bn + wx * WTN + nt * 8 + t4 * 2;
            epi(r0,     c, acc[mt][nt][0], acc[mt][nt][1]);
            epi(r0 + 8, c, acc[mt][nt][2], acc[mt][nt][3]);
        }
    }
}

// ---------------- LayerNorm over D=256, 128 threads x float2 ----------------
template<bool ADD, bool WF, bool WS>
__global__ void ln_k(const float* __restrict__ x, const float* __restrict__ add,
                     const float* __restrict__ g, const float* __restrict__ b,
                     float* __restrict__ outf, uint32_t* __restrict__ ohi,
                     uint32_t* __restrict__ olo)
{
    int t = blockIdx.x;
    int tid = threadIdx.x;    // 128
    float2 v = reinterpret_cast<const float2*>(x + (size_t)t * DD)[tid];
    if (ADD) {
        float2 a2 = reinterpret_cast<const float2*>(add + (size_t)t * DD)[tid];
        v.x += a2.x; v.y += a2.y;
    }
    float s = v.x + v.y, q = v.x * v.x + v.y * v.y;
#pragma unroll
    for (int o = 16; o > 0; o >>= 1) {
        s += __shfl_xor_sync(0xffffffffu, s, o);
        q += __shfl_xor_sync(0xffffffffu, q, o);
    }
    __shared__ float ws[4], wq[4];
    int w = tid >> 5, lane = tid & 31;
    if (lane == 0) { ws[w] = s; wq[w] = q; }
    __syncthreads();
    float ts = ws[0] + ws[1] + ws[2] + ws[3];
    float tq = wq[0] + wq[1] + wq[2] + wq[3];
    float mean = ts * (1.f / DD);
    float var  = tq * (1.f / DD) - mean * mean;
    float r = rsqrtf(var + 1e-5f);
    float2 gg = reinterpret_cast<const float2*>(g)[tid];
    float2 bb = reinterpret_cast<const float2*>(b)[tid];
    float y0 = (v.x - mean) * r * gg.x + bb.x;
    float y1 = (v.y - mean) * r * gg.y + bb.y;
    if (WF) {
        float2 o; o.x = y0; o.y = y1;
        reinterpret_cast<float2*>(outf + (size_t)t * DD)[tid] = o;
    }
    if (WS) {
        uint32_t h, l;
        split_pair(y0, y1, h, l);
        ohi[(size_t)t * (DD / 2) + tid] = h;
        olo[(size_t)t * (DD / 2) + tid] = l;
    }
}

// ---------------- flash-style causal attention ----------------
__global__ __launch_bounds__(256, 2)
void attn_k(const float* __restrict__ qkv, float* __restrict__ att)
{
    constexpr int KT = 64;
    constexpr int VST = 36;
    __shared__ float Ks[KT * VST];
    __shared__ float Vs[KT * VST];

    const int qt = blockIdx.x, h = blockIdx.y, b = blockIdx.z;
    const int tid = threadIdx.x;
    const int r = tid >> 1, half = tid & 1;
    const int qg = qt * 128 + r;

    const float* base = qkv + (size_t)(b * SS) * (3 * DD);
    const float scale = rsqrtf((float)DHH);

    float qreg[DHH];
    {
        const float4* qp = reinterpret_cast<const float4*>(base + (size_t)qg * (3 * DD) + h * DHH);
#pragma unroll
        for (int i = 0; i < 8; i++) {
            float4 f = qp[i];
            qreg[i*4+0] = f.x * scale; qreg[i*4+1] = f.y * scale;
            qreg[i*4+2] = f.z * scale; qreg[i*4+3] = f.w * scale;
        }
    }

    float m = -1e30f, lsum = 0.f;
    float o[DHH];
#pragma unroll
    for (int d = 0; d < DHH; d++) o[d] = 0.f;

    const int ntiles = (qt + 1) * 2;
    for (int kt = 0; kt < ntiles; kt++) {
#pragma unroll
        for (int it = 0; it < 2; it++) {
            int idx = tid + it * 256;
            int rr = idx >> 3, c = idx & 7;
            int k = kt * KT + rr;
            const float4* kp = reinterpret_cast<const float4*>(base + (size_t)k * (3 * DD) + DD + h * DHH);
            const float4* vp = reinterpret_cast<const float4*>(base + (size_t)k * (3 * DD) + 2 * DD + h * DHH);
            *reinterpret_cast<float4*>(&Ks[rr * VST + c * 4]) = kp[c];
            *reinterpret_cast<float4*>(&Vs[rr * VST + c * 4]) = vp[c];
        }
        __syncthreads();

        const int kbase = kt * KT + half * 32;
        if (kbase <= qg) {
            float p[32];
            float smax = -1e30f;
#pragma unroll 4
            for (int kk = 0; kk < 32; kk++) {
                const float* kr = &Ks[(half * 32 + kk) * VST];
                float dot = 0.f;
#pragma unroll
                for (int d = 0; d < DHH; d++) dot = fmaf(qreg[d], kr[d], dot);
                if (kbase + kk > qg) dot = -1e30f;
                p[kk] = dot;
                smax = fmaxf(smax, dot);
            }
            float newm = fmaxf(m, smax);
            float f = __expf(m - newm);
            float ls = 0.f;
#pragma unroll
            for (int kk = 0; kk < 32; kk++) {
                p[kk] = __expf(p[kk] - newm);
                ls += p[kk];
            }
            lsum = lsum * f + ls;
#pragma unroll
            for (int d = 0; d < DHH; d++) o[d] *= f;
#pragma unroll 4
            for (int kk = 0; kk < 32; kk++) {
                const float* vr = &Vs[(half * 32 + kk) * VST];
                float pk = p[kk];
#pragma unroll
                for (int d = 0; d < DHH; d++) o[d] = fmaf(pk, vr[d], o[d]);
            }
            m = newm;
        }
        __syncthreads();
    }

    float om = __shfl_xor_sync(0xffffffffu, m, 1);
    float nm = fmaxf(m, om);
    float fs = __expf(m - nm);
    float lS = lsum * fs;
    float lT = lS + __shfl_xor_sync(0xffffffffu, lS, 1);
    float inv = 1.f / lT;
    float* op = att + (size_t)(b * SS + qg) * DD + h * DHH;
#pragma unroll
    for (int d = 0; d < DHH; d++) {
        float oS = o[d] * fs;
        float oT = oS + __shfl_xor_sync(0xffffffffu, oS, 1);
        if (half == 0) op[d] = oT * inv;
    }
}

// ---------------- global normalize (mean / std ddof=1, + 1e-10) ----------------
__global__ void zero_red_k() { g_red[0] = 0.0; g_red[1] = 0.0; }

__global__ void reduce_k(const float* __restrict__ x, int n)
{
    double s = 0.0, q = 0.0;
    for (int i = blockIdx.x * blockDim.x + threadIdx.x; i < n; i += gridDim.x * blockDim.x) {
        double v = (double)x[i];
        s += v; q += v * v;
    }
#pragma unroll
    for (int o = 16; o > 0; o >>= 1) {
        s += __shfl_xor_sync(0xffffffffu, s, o);
        q += __shfl_xor_sync(0xffffffffu, q, o);
    }
    __shared__ double ws[8], wq[8];
    int w = threadIdx.x >> 5, lane = threadIdx.x & 31;
    if (lane == 0) { ws[w] = s; wq[w] = q; }
    __syncthreads();
    if (threadIdx.x == 0) {
        double ts = 0.0, tq = 0.0;
        for (int i = 0; i < (int)(blockDim.x / 32); i++) { ts += ws[i]; tq += wq[i]; }
        atomicAdd(&g_red[0], ts);
        atomicAdd(&g_red[1], tq);
    }
}

__global__ void stats_k(int n)
{
    double mean = g_red[0] / n;
    double var = (g_red[1] - (double)n * mean * mean) / (double)(n - 1);
    g_stats[0] = (float)mean;
    g_stats[1] = (float)(1.0 / sqrt(var));
}

__global__ void norm_k(float* __restrict__ x, int n)
{
    int i = blockIdx.x * blockDim.x + threadIdx.x;
    if (i < n) x[i] = (x[i] - g_stats[0]) * g_stats[1] + 1e-10f;
}

// ---------------- host-side launch helpers ----------------
template<int BM, int WY, int WX, int ACT, int OMODE, bool ACCUM, bool ADDROW>
static void launch_gemm(const uint32_t* Ah, const uint32_t* Al,
                        const uint32_t* Bh, const uint32_t* Bl,
                        const float* bias, const float* ra,
                        float* C, uint32_t* Chi, uint32_t* Clo,
                        int M, int N, int K2)
{
    constexpr int BN = 128, ST = 20;
    int smem = 2 * (2 * BM + 2 * BN) * ST * 4;
    auto kfn = gemm_bs<BM, BN, WY, WX, ACT, OMODE, ACCUM, ADDROW>;
    cudaFuncSetAttribute(kfn, cudaFuncAttributeMaxDynamicSharedMemorySize, smem);
    kfn<<<dim3(N / BN, M / BM), 256, smem>>>(Ah, Al, Bh, Bl, bias, ra, C, Chi, Clo, M, N, K2);
}

static void wsplit(const float* W, uint32_t* hi, uint32_t* lo, int K2, int N,
                   int layers = 1, size_t wstride = 0, size_t ostride = 0)
{
    wsplit_b<<<dim3(K2 / 32, N / 32, layers), dim3(32, 8)>>>(W, hi, lo, K2, N, wstride, ostride);
}

extern "C" void kernel_launch(void* const* d_in, const int* in_sizes, int n_in,
                              void* d_out, int out_size)
{
    const float* state  = (const float*)d_in[0];
    const float* fc1_w  = (const float*)d_in[1];
    const float* fc1_b  = (const float*)d_in[2];
    const float* fc2_w  = (const float*)d_in[3];
    const float* fc2_b  = (const float*)d_in[4];
    const float* fc3_w  = (const float*)d_in[5];
    const float* fc3_b  = (const float*)d_in[6];
    const float* fc4_w  = (const float*)d_in[7];
    const float* fc4_b  = (const float*)d_in[8];
    const float* fc5_w  = (const float*)d_in[9];
    const float* fc5_b  = (const float*)d_in[10];
    const float* pre_w  = (const float*)d_in[11];
    const float* pre_b  = (const float*)d_in[12];
    const float* pos_w  = (const float*)d_in[13];
    const float* enc_w  = (const float*)d_in[14];
    const float* enc_b  = (const float*)d_in[15];
    const float* ln1_g  = (const float*)d_in[16];
    const float* ln1_b  = (const float*)d_in[17];
    const float* ln2_g  = (const float*)d_in[18];
    const float* ln2_b  = (const float*)d_in[19];
    const float* res_w1 = (const float*)d_in[20];
    const float* res_b1 = (const float*)d_in[21];
    const float* res_w2 = (const float*)d_in[22];
    const float* res_b2 = (const float*)d_in[23];
    const float* out_w  = (const float*)d_in[24];
    const float* out_b  = (const float*)d_in[25];
    float* out = (float*)d_out;

    uint32_t *wh, *wl, *ah1, *al1, *ah2, *al2;
    float *x, *qkv, *att;
    cudaGetSymbolAddress((void**)&wh,  g_wh);
    cudaGetSymbolAddress((void**)&wl,  g_wl);
    cudaGetSymbolAddress((void**)&ah1, g_ah1);
    cudaGetSymbolAddress((void**)&al1, g_al1);
    cudaGetSymbolAddress((void**)&ah2, g_ah2);
    cudaGetSymbolAddress((void**)&al2, g_al2);
    cudaGetSymbolAddress((void**)&x,   g_x);
    cudaGetSymbolAddress((void**)&qkv, g_qkv);
    cudaGetSymbolAddress((void**)&att, g_att);

    const int M = TOK;

    // ---- weight transpose+splits -> [N][K2] (per-layer ones batched via grid.z) ----
    wsplit(fc1_w, wh + W1_OFF,   wl + W1_OFF,   2048, 4096);
    wsplit(fc2_w, wh + W2_OFF,   wl + W2_OFF,   2048, 2048);
    wsplit(fc3_w, wh + W3_OFF,   wl + W3_OFF,   1024, 1024);
    wsplit(fc4_w, wh + W4_OFF,   wl + W4_OFF,    512,  512);
    wsplit(fc5_w, wh + W5_OFF,   wl + W5_OFF,    256,  256);
    wsplit(pre_w, wh + WPRE_OFF, wl + WPRE_OFF,  128,  256);
    wsplit(enc_w,  wh + WENC_OFF, wl + WENC_OFF, 128,  768, NBLK, 256 * 768,  98304);
    wsplit(res_w1, wh + WR1_OFF,  wl + WR1_OFF,  128, 1024, NBLK, 256 * 1024, 131072);
    wsplit(res_w2, wh + WR2_OFF,  wl + WR2_OFF,  512,  256, NBLK, 1024 * 256, 131072);
    wsplit(out_w, wh + WOUT_OFF, wl + WOUT_OFF, 128, 128);

    // ---- input split ----
    asplit_k<<<(M * 2048 + 255) / 256, 256>>>(state, ah1, al1, M * 2048);

    // ---- MLP stack (split in -> split out) ----
    launch_gemm<128, 2, 4, 1, 1, false, false>(ah1, al1, wh + W1_OFF, wl + W1_OFF,
        fc1_b, nullptr, nullptr, ah2, al2, M, 4096, 2048);
    launch_gemm<128, 2, 4, 1, 1, false, false>(ah2, al2, wh + W2_OFF, wl + W2_OFF,
        fc2_b, nullptr, nullptr, ah1, al1, M, 2048, 2048);
    launch_gemm<128, 2, 4, 1, 1, false, false>(ah1, al1, wh + W3_OFF, wl + W3_OFF,
        fc3_b, nullptr, nullptr, ah2, al2, M, 1024, 1024);
    launch_gemm<128, 2, 4, 1, 1, false, false>(ah2, al2, wh + W4_OFF, wl + W4_OFF,
        fc4_b, nullptr, nullptr, ah1, al1, M, 512, 512);
    launch_gemm<64, 1, 8, 2, 1, false, false>(ah1, al1, wh + W5_OFF, wl + W5_OFF,
        fc5_b, nullptr, nullptr, ah2, al2, M, 256, 256);
    launch_gemm<64, 1, 8, 0, 0, false, true>(ah2, al2, wh + WPRE_OFF, wl + WPRE_OFF,
        pre_b, pos_w, x, nullptr, nullptr, M, 256, 128);

    // ---- transformer blocks ----
    for (int l = 0; l < NBLK; l++) {
        ln_k<false, false, true><<<TOK, 128>>>(x, nullptr, ln1_g + l * DD, ln1_b + l * DD,
                                               nullptr, ah1, al1);
        launch_gemm<128, 2, 4, 0, 0, false, false>(ah1, al1,
            wh + WENC_OFF + (size_t)l * 98304, wl + WENC_OFF + (size_t)l * 98304,
            enc_b + l * 3 * DD, nullptr, qkv, nullptr, nullptr, M, 768, 128);
        attn_k<<<dim3(SS / 128, HH, BB), 256>>>(qkv, att);
        ln_k<true, true, true><<<TOK, 128>>>(x, att, ln2_g + l * DD, ln2_b + l * DD,
                                             x, ah1, al1);
        launch_gemm<128, 2, 4, 3, 1, false, false>(ah1, al1,
            wh + WR1_OFF + (size_t)l * 131072, wl + WR1_OFF + (size_t)l * 131072,
            res_b1 + l * 4 * DD, nullptr, nullptr, ah2, al2, M, 1024, 128);
        launch_gemm<64, 1, 8, 0, 0, true, false>(ah2, al2,
            wh + WR2_OFF + (size_t)l * 131072, wl + WR2_OFF + (size_t)l * 131072,
            res_b2 + l * DD, nullptr, x, nullptr, nullptr, M, 256, 512);
    }

    // ---- output projection + global normalize ----
    asplit_k<<<(M * 128 + 255) / 256, 256>>>(x, ah1, al1, M * 128);
    launch_gemm<64, 1, 8, 0, 0, false, false>(ah1, al1, wh + WOUT_OFF, wl + WOUT_OFF,
        out_b, nullptr, out, nullptr, nullptr, M, 128, 128);

    int n = TOK * 128;
    zero_red_k<<<1, 1>>>();
    reduce_k<<<256, 256>>>(out, n);
    stats_k<<<1, 1>>>(n);
    norm_k<<<(n + 255) / 256, 256>>>(out, n);
}

// round 11
// speedup vs baseline: 4.3319x; 1.1562x over previous
#include <cuda_runtime.h>
#include <cuda_bf16.h>
#include <math.h>
#include <stdint.h>

// Problem dims
#define BB 8
#define SS 512
#define DD 256
#define HH 8
#define DHH 32
#define NBLK 8
#define TOK (BB*SS)          // 4096 tokens

// ---------------- device scratch ----------------
// weight split arenas: stage-tiled [k-stage][N][16 u32], chunk-swizzled
#define W1_OFF   0u
#define W1_SZ    (2048u*4096u)
#define W2_OFF   (W1_OFF + W1_SZ)
#define W2_SZ    (2048u*2048u)
#define W3_OFF   (W2_OFF + W2_SZ)
#define W3_SZ    (1024u*1024u)
#define W4_OFF   (W3_OFF + W3_SZ)
#define W4_SZ    (512u*512u)
#define W5_OFF   (W4_OFF + W4_SZ)
#define W5_SZ    (256u*256u)
#define WPRE_OFF (W5_OFF + W5_SZ)
#define WPRE_SZ  (128u*256u)
#define WENC_OFF (WPRE_OFF + WPRE_SZ)
#define WENC_SZ  (1024u*768u)
#define WR1_OFF  (WENC_OFF + WENC_SZ)
#define WR1_SZ   (1024u*1024u)
#define WR2_OFF  (WR1_OFF + WR1_SZ)
#define WR2_SZ   (4096u*256u)
#define WOUT_OFF (WR2_OFF + WR2_SZ)
#define WOUT_SZ  (128u*128u)
#define WARENA   (WOUT_OFF + WOUT_SZ)

__device__ uint32_t g_wh[WARENA];
__device__ uint32_t g_wl[WARENA];

// activation split ping-pong arenas (stage-tiled), max 4096 x 2048 u32
__device__ uint32_t g_ah1[4096u*2048u];
__device__ uint32_t g_al1[4096u*2048u];
__device__ uint32_t g_ah2[4096u*2048u];
__device__ uint32_t g_al2[4096u*2048u];

__device__ float g_x  [TOK * DD];
__device__ float g_qkv[TOK * 3 * DD];
__device__ float g_att[TOK * DD];
__device__ double g_red[2];
__device__ float g_stats[2];

// ---------------- bf16 split helpers ----------------
__device__ __forceinline__ void split_pair(float x, float y, uint32_t& hi, uint32_t& lo)
{
    __nv_bfloat16 hx = __float2bfloat16_rn(x);
    __nv_bfloat16 hy = __float2bfloat16_rn(y);
    float rx = x - __bfloat162float(hx);
    float ry = y - __bfloat162float(hy);
    __nv_bfloat162 h2; h2.x = hx; h2.y = hy;
    __nv_bfloat162 l2; l2.x = __float2bfloat16_rn(rx); l2.y = __float2bfloat16_rn(ry);
    hi = *reinterpret_cast<uint32_t*>(&h2);
    lo = *reinterpret_cast<uint32_t*>(&l2);
}

__device__ __forceinline__ void mma16816(float* c, const uint32_t* a, const uint32_t* b)
{
    asm volatile(
        "mma.sync.aligned.m16n8k16.row.col.f32.bf16.bf16.f32 "
        "{%0,%1,%2,%3},{%4,%5,%6,%7},{%8,%9},{%0,%1,%2,%3};"
        : "+f"(c[0]), "+f"(c[1]), "+f"(c[2]), "+f"(c[3])
        : "r"(a[0]), "r"(a[1]), "r"(a[2]), "r"(a[3]), "r"(b[0]), "r"(b[1]));
}

__device__ __forceinline__ void ldsm4(uint32_t* r, uint32_t addr)
{
    asm volatile("ldmatrix.sync.aligned.m8n8.x4.shared.b16 {%0,%1,%2,%3},[%4];"
                 : "=r"(r[0]), "=r"(r[1]), "=r"(r[2]), "=r"(r[3]) : "r"(addr));
}

__device__ __forceinline__ uint32_t smem_u32(const void* p)
{
    uint32_t a;
    asm("{ .reg .u64 t; cvta.to.shared.u64 t, %1; cvt.u32.u64 %0, t; }" : "=r"(a) : "l"(p));
    return a;
}

__device__ __forceinline__ void mbar_init(uint32_t addr, uint32_t cnt)
{
    asm volatile("mbarrier.init.shared.b64 [%0], %1;" :: "r"(addr), "r"(cnt) : "memory");
}

__device__ __forceinline__ void mbar_expect_tx(uint32_t addr, uint32_t bytes)
{
    asm volatile("mbarrier.arrive.expect_tx.shared.b64 _, [%0], %1;"
                 :: "r"(addr), "r"(bytes) : "memory");
}

__device__ __forceinline__ void mbar_wait(uint32_t addr, uint32_t parity)
{
    uint32_t done;
    asm volatile("{\n\t.reg .pred p;\n\t"
        "mbarrier.try_wait.parity.acquire.cta.shared::cta.b64 p, [%1], %2;\n\t"
        "selp.b32 %0,1,0,p;\n\t}" : "=r"(done) : "r"(addr), "r"(parity) : "memory");
    while (!done) {
        asm volatile("{\n\t.reg .pred p;\n\t"
            "mbarrier.try_wait.parity.acquire.cta.shared::cta.b64 p, [%1], %2, 0x989680;\n\t"
            "selp.b32 %0,1,0,p;\n\t}" : "=r"(done) : "r"(addr), "r"(parity) : "memory");
    }
}

// 1D bulk async copy global -> shared, mbarrier transaction completion
__device__ __forceinline__ void bulkcp(uint32_t sdst, const void* gsrc, uint32_t bytes, uint32_t bar)
{
    asm volatile(
        "cp.async.bulk.shared::cluster.global.mbarrier::complete_tx::bytes [%0], [%1], %2, [%3];"
        :: "r"(sdst), "l"(gsrc), "r"(bytes), "r"(bar) : "memory");
}

// stage-tiled global index for pair kp of row m (rows-per-matrix = R)
// layout: [kp/16][m][16], 16B chunk swizzle c ^= (m>>1)&3
__device__ __forceinline__ size_t tile_idx(int m, int kp, int R)
{
    int sdx = kp >> 4, cc = (kp >> 2) & 3, ii = kp & 3;
    return ((size_t)sdx * R + m) * 16 + (size_t)(((cc ^ ((m >> 1) & 3)) << 2) + ii);
}

// ---------------- split kernels ----------------
// weight transpose+split: fp32 [K][N] -> hi/lo stage-tiled [K2/16][N][16]
__global__ void wsplit_b(const float* __restrict__ W0, uint32_t* __restrict__ hi0,
                         uint32_t* __restrict__ lo0, int K2, int N,
                         size_t wstride, size_t ostride)
{
    const float* W = W0 + (size_t)blockIdx.z * wstride;
    uint32_t* hi = hi0 + (size_t)blockIdx.z * ostride;
    uint32_t* lo = lo0 + (size_t)blockIdx.z * ostride;
    __shared__ uint32_t sh[32][33], sl[32][33];
    int kp0 = blockIdx.x * 32, n0 = blockIdx.y * 32;
    int tx = threadIdx.x, ty = threadIdx.y;   // (32,8)
#pragma unroll
    for (int i = ty; i < 32; i += 8) {
        int kp = kp0 + i;
        float f0 = W[(size_t)(2 * kp)     * N + n0 + tx];
        float f1 = W[(size_t)(2 * kp + 1) * N + n0 + tx];
        uint32_t h, l;
        split_pair(f0, f1, h, l);
        sh[i][tx] = h; sl[i][tx] = l;
    }
    __syncthreads();
#pragma unroll
    for (int j = ty; j < 32; j += 8) {
        int n = n0 + j;
        int kp = kp0 + tx;
        size_t o = tile_idx(n, kp, N);
        hi[o] = sh[tx][j];
        lo[o] = sl[tx][j];
    }
}

// activation: fp32 row-major [M][K] -> stage-tiled split
__global__ void asplit_k(const float* __restrict__ A, uint32_t* __restrict__ hi,
                         uint32_t* __restrict__ lo, int M, int K2)
{
    int idx = blockIdx.x * blockDim.x + threadIdx.x;
    if (idx >= M * K2) return;
    int m = idx / K2, kp = idx % K2;
    float2 v = reinterpret_cast<const float2*>(A)[idx];
    uint32_t h, l;
    split_pair(v.x, v.y, h, l);
    size_t o = tile_idx(m, kp, M);
    hi[o] = h; lo[o] = l;
}

// ---------------- tensor-core GEMM, bf16x3, TMA-bulk 3-stage + ldmatrix ----------------
// A: hi/lo stage-tiled [K2/16][M][16], B: hi/lo stage-tiled [K2/16][N][16]
// BM=BN=128, 128 threads (4 warps, 64x64 warp tiles), 2 CTA/SM.
// OMODE: 0 = write fp32 C, 1 = write split stage-tiled Chi/Clo
template<int ACT, int OMODE, bool ACCUM, bool ADDROW>
__global__ __launch_bounds__(128, 2)
void gemm_tma(const uint32_t* __restrict__ Ahg, const uint32_t* __restrict__ Alg,
              const uint32_t* __restrict__ Bhg, const uint32_t* __restrict__ Blg,
              const float* __restrict__ bias, const float* __restrict__ rowadd,
              float* __restrict__ C, uint32_t* __restrict__ Chi, uint32_t* __restrict__ Clo,
              int M, int N, int K2)
{
    constexpr int NBUF = 3;
    constexpr int STG = 32768;           // bytes per stage: 4 operands x 8KB
    constexpr int MT = 4, NT = 8;        // warp tile 64x64

    extern __shared__ uint8_t dyn[];
    __shared__ __align__(8) uint64_t s_mbar[NBUF];

    const uint32_t dbase = smem_u32(dyn);
    const uint32_t mb = smem_u32(s_mbar);
    const int tid = threadIdx.x;
    const int lane = tid & 31;
    const int warp = tid >> 5;           // 0..3
    const int wy = warp >> 1, wx = warp & 1;
    const int bm = blockIdx.y * 128, bn = blockIdx.x * 128;
    const int g = lane >> 2, t4 = lane & 3;

    if (tid == 0) {
#pragma unroll
        for (int i = 0; i < NBUF; i++) mbar_init(mb + i * 8, 1);
    }
    __syncthreads();

    const int NS = K2 >> 4;

    auto issue = [&](int s) {
        const uint32_t sb = dbase + (uint32_t)(s % NBUF) * STG;
        const uint32_t bar = mb + (uint32_t)(s % NBUF) * 8;
        mbar_expect_tx(bar, 32768u);
        bulkcp(sb,         Ahg + (size_t)(s * M + bm) * 16, 8192, bar);
        bulkcp(sb + 8192,  Alg + (size_t)(s * M + bm) * 16, 8192, bar);
        bulkcp(sb + 16384, Bhg + (size_t)(s * N + bn) * 16, 8192, bar);
        bulkcp(sb + 24576, Blg + (size_t)(s * N + bn) * 16, 8192, bar);
    };

    float acc[MT][NT][4];
#pragma unroll
    for (int i = 0; i < MT; i++)
#pragma unroll
        for (int j = 0; j < NT; j++)
#pragma unroll
            for (int r = 0; r < 4; r++) acc[i][j][r] = 0.f;

    // per-thread ldsm row bases + swizzle keys
    uint32_t rA[MT]; int swA[MT];
    const int cbA = lane >> 4;
#pragma unroll
    for (int mt = 0; mt < MT; mt++) {
        int r = wy * 64 + mt * 16 + (lane & 15);
        rA[mt] = (uint32_t)r * 64;
        swA[mt] = (r >> 1) & 3;
    }
    const int q = lane >> 3;
    const int cbB = q & 1;
    uint32_t rB[4]; int swB[4];
#pragma unroll
    for (int p = 0; p < 4; p++) {
        int r = wx * 64 + p * 16 + ((q >> 1) << 3) + (lane & 7);
        rB[p] = (uint32_t)r * 64;
        swB[p] = (r >> 1) & 3;
    }

    if (tid == 0) {
        int pre = NS < NBUF ? NS : NBUF;
        for (int s = 0; s < pre; s++) issue(s);
    }

    for (int s = 0; s < NS; s++) {
        const int slot = s % NBUF;
        mbar_wait(mb + slot * 8, (uint32_t)((s / NBUF) & 1));
        const uint32_t s0 = dbase + (uint32_t)slot * STG;
#pragma unroll
        for (int kk = 0; kk < 2; kk++) {
            uint32_t ah[MT][4], al[MT][4], bh[NT][2], bl[NT][2];
            const int k2c = kk * 2;
#pragma unroll
            for (int mt = 0; mt < MT; mt++) {
                uint32_t ch = (uint32_t)((k2c + cbA) ^ swA[mt]) * 16;
                ldsm4(ah[mt], s0 + rA[mt] + ch);
                ldsm4(al[mt], s0 + 8192 + rA[mt] + ch);
            }
#pragma unroll
            for (int p = 0; p < 4; p++) {
                uint32_t ch = (uint32_t)((k2c + cbB) ^ swB[p]) * 16;
                uint32_t t[4];
                ldsm4(t, s0 + 16384 + rB[p] + ch);
                bh[2*p][0] = t[0]; bh[2*p][1] = t[1];
                bh[2*p+1][0] = t[2]; bh[2*p+1][1] = t[3];
                ldsm4(t, s0 + 24576 + rB[p] + ch);
                bl[2*p][0] = t[0]; bl[2*p][1] = t[1];
                bl[2*p+1][0] = t[2]; bl[2*p+1][1] = t[3];
            }
#pragma unroll
            for (int mt = 0; mt < MT; mt++)
#pragma unroll
                for (int nt = 0; nt < NT; nt++) {
                    mma16816(acc[mt][nt], ah[mt], bh[nt]);  // hi*hi
                    mma16816(acc[mt][nt], ah[mt], bl[nt]);  // hi*lo
                    mma16816(acc[mt][nt], al[mt], bh[nt]);  // lo*hi
                }
        }
        __syncthreads();
        if (tid == 0 && s + NBUF < NS) issue(s + NBUF);
    }

    // --- epilogue: pairs (col, col+1) ---
    auto epi = [&](int row, int col, float v0, float v1) {
        v0 += bias[col]; v1 += bias[col + 1];
        if (ADDROW) {
            const float* ra = rowadd + (size_t)(row % SS) * N + col;
            v0 += ra[0]; v1 += ra[1];
        }
        if (ACT == 1) { v0 = fmaxf(v0, 0.f); v1 = fmaxf(v1, 0.f); }
        else if (ACT == 2) { v0 = tanhf(v0); v1 = tanhf(v1); }
        else if (ACT == 3) {
            v0 = 0.5f * v0 * (1.f + erff(v0 * 0.70710678118654752f));
            v1 = 0.5f * v1 * (1.f + erff(v1 * 0.70710678118654752f));
        }
        if (OMODE == 0) {
            float* cp = C + (size_t)row * N + col;
            if (ACCUM) { cp[0] += v0; cp[1] += v1; }
            else       { float2 o; o.x = v0; o.y = v1; *reinterpret_cast<float2*>(cp) = o; }
        } else {
            uint32_t h, l;
            split_pair(v0, v1, h, l);
            size_t o = tile_idx(row, col >> 1, M);
            Chi[o] = h; Clo[o] = l;
        }
    };

#pragma unroll
    for (int mt = 0; mt < MT; mt++) {
        int r0 = bm + wy * 64 + mt * 16 + g;
#pragma unroll
        for (int nt = 0; nt < NT; nt++) {
            int c = bn + wx * 64 + nt * 8 + t4 * 2;
            epi(r0,     c, acc[mt][nt][0], acc[mt][nt][1]);
            epi(r0 + 8, c, acc[mt][nt][2], acc[mt][nt][3]);
        }
    }
}

// ---------------- LayerNorm over D=256, 128 threads x float2 ----------------
template<bool ADD, bool WF, bool WS>
__global__ void ln_k(const float* __restrict__ x, const float* __restrict__ add,
                     const float* __restrict__ g, const float* __restrict__ b,
                     float* __restrict__ outf, uint32_t* __restrict__ ohi,
                     uint32_t* __restrict__ olo)
{
    int t = blockIdx.x;
    int tid = threadIdx.x;    // 128
    float2 v = reinterpret_cast<const float2*>(x + (size_t)t * DD)[tid];
    if (ADD) {
        float2 a2 = reinterpret_cast<const float2*>(add + (size_t)t * DD)[tid];
        v.x += a2.x; v.y += a2.y;
    }
    float s = v.x + v.y, q = v.x * v.x + v.y * v.y;
#pragma unroll
    for (int o = 16; o > 0; o >>= 1) {
        s += __shfl_xor_sync(0xffffffffu, s, o);
        q += __shfl_xor_sync(0xffffffffu, q, o);
    }
    __shared__ float ws[4], wq[4];
    int w = tid >> 5, lane = tid & 31;
    if (lane == 0) { ws[w] = s; wq[w] = q; }
    __syncthreads();
    float ts = ws[0] + ws[1] + ws[2] + ws[3];
    float tq = wq[0] + wq[1] + wq[2] + wq[3];
    float mean = ts * (1.f / DD);
    float var  = tq * (1.f / DD) - mean * mean;
    float r = rsqrtf(var + 1e-5f);
    float2 gg = reinterpret_cast<const float2*>(g)[tid];
    float2 bb = reinterpret_cast<const float2*>(b)[tid];
    float y0 = (v.x - mean) * r * gg.x + bb.x;
    float y1 = (v.y - mean) * r * gg.y + bb.y;
    if (WF) {
        float2 o; o.x = y0; o.y = y1;
        reinterpret_cast<float2*>(outf + (size_t)t * DD)[tid] = o;
    }
    if (WS) {
        uint32_t h, l;
        split_pair(y0, y1, h, l);
        size_t o = tile_idx(t, tid, TOK);
        ohi[o] = h; olo[o] = l;
    }
}

// ---------------- flash-style causal attention ----------------
__global__ __launch_bounds__(256, 2)
void attn_k(const float* __restrict__ qkv, float* __restrict__ att)
{
    constexpr int KT = 64;
    constexpr int VST = 36;
    __shared__ float Ks[KT * VST];
    __shared__ float Vs[KT * VST];

    const int qt = blockIdx.x, h = blockIdx.y, b = blockIdx.z;
    const int tid = threadIdx.x;
    const int r = tid >> 1, half = tid & 1;
    const int qg = qt * 128 + r;

    const float* base = qkv + (size_t)(b * SS) * (3 * DD);
    const float scale = rsqrtf((float)DHH);

    float qreg[DHH];
    {
        const float4* qp = reinterpret_cast<const float4*>(base + (size_t)qg * (3 * DD) + h * DHH);
#pragma unroll
        for (int i = 0; i < 8; i++) {
            float4 f = qp[i];
            qreg[i*4+0] = f.x * scale; qreg[i*4+1] = f.y * scale;
            qreg[i*4+2] = f.z * scale; qreg[i*4+3] = f.w * scale;
        }
    }

    float m = -1e30f, lsum = 0.f;
    float o[DHH];
#pragma unroll
    for (int d = 0; d < DHH; d++) o[d] = 0.f;

    const int ntiles = (qt + 1) * 2;
    for (int kt = 0; kt < ntiles; kt++) {
#pragma unroll
        for (int it = 0; it < 2; it++) {
            int idx = tid + it * 256;
            int rr = idx >> 3, c = idx & 7;
            int k = kt * KT + rr;
            const float4* kp = reinterpret_cast<const float4*>(base + (size_t)k * (3 * DD) + DD + h * DHH);
            const float4* vp = reinterpret_cast<const float4*>(base + (size_t)k * (3 * DD) + 2 * DD + h * DHH);
            *reinterpret_cast<float4*>(&Ks[rr * VST + c * 4]) = kp[c];
            *reinterpret_cast<float4*>(&Vs[rr * VST + c * 4]) = vp[c];
        }
        __syncthreads();

        const int kbase = kt * KT + half * 32;
        if (kbase <= qg) {
            float p[32];
            float smax = -1e30f;
#pragma unroll 4
            for (int kk = 0; kk < 32; kk++) {
                const float* kr = &Ks[(half * 32 + kk) * VST];
                float dot = 0.f;
#pragma unroll
                for (int d = 0; d < DHH; d++) dot = fmaf(qreg[d], kr[d], dot);
                if (kbase + kk > qg) dot = -1e30f;
                p[kk] = dot;
                smax = fmaxf(smax, dot);
            }
            float newm = fmaxf(m, smax);
            float f = __expf(m - newm);
            float ls = 0.f;
#pragma unroll
            for (int kk = 0; kk < 32; kk++) {
                p[kk] = __expf(p[kk] - newm);
                ls += p[kk];
            }
            lsum = lsum * f + ls;
#pragma unroll
            for (int d = 0; d < DHH; d++) o[d] *= f;
#pragma unroll 4
            for (int kk = 0; kk < 32; kk++) {
                const float* vr = &Vs[(half * 32 + kk) * VST];
                float pk = p[kk];
#pragma unroll
                for (int d = 0; d < DHH; d++) o[d] = fmaf(pk, vr[d], o[d]);
            }
            m = newm;
        }
        __syncthreads();
    }

    float om = __shfl_xor_sync(0xffffffffu, m, 1);
    float nm = fmaxf(m, om);
    float fs = __expf(m - nm);
    float lS = lsum * fs;
    float lT = lS + __shfl_xor_sync(0xffffffffu, lS, 1);
    float inv = 1.f / lT;
    float* op = att + (size_t)(b * SS + qg) * DD + h * DHH;
#pragma unroll
    for (int d = 0; d < DHH; d++) {
        float oS = o[d] * fs;
        float oT = oS + __shfl_xor_sync(0xffffffffu, oS, 1);
        if (half == 0) op[d] = oT * inv;
    }
}

// ---------------- global normalize (mean / std ddof=1, + 1e-10) ----------------
__global__ void zero_red_k() { g_red[0] = 0.0; g_red[1] = 0.0; }

__global__ void reduce_k(const float* __restrict__ x, int n)
{
    double s = 0.0, q = 0.0;
    for (int i = blockIdx.x * blockDim.x + threadIdx.x; i < n; i += gridDim.x * blockDim.x) {
        double v = (double)x[i];
        s += v; q += v * v;
    }
#pragma unroll
    for (int o = 16; o > 0; o >>= 1) {
        s += __shfl_xor_sync(0xffffffffu, s, o);
        q += __shfl_xor_sync(0xffffffffu, q, o);
    }
    __shared__ double ws[8], wq[8];
    int w = threadIdx.x >> 5, lane = threadIdx.x & 31;
    if (lane == 0) { ws[w] = s; wq[w] = q; }
    __syncthreads();
    if (threadIdx.x == 0) {
        double ts = 0.0, tq = 0.0;
        for (int i = 0; i < (int)(blockDim.x / 32); i++) { ts += ws[i]; tq += wq[i]; }
        atomicAdd(&g_red[0], ts);
        atomicAdd(&g_red[1], tq);
    }
}

__global__ void stats_k(int n)
{
    double mean = g_red[0] / n;
    double var = (g_red[1] - (double)n * mean * mean) / (double)(n - 1);
    g_stats[0] = (float)mean;
    g_stats[1] = (float)(1.0 / sqrt(var));
}

__global__ void norm_k(float* __restrict__ x, int n)
{
    int i = blockIdx.x * blockDim.x + threadIdx.x;
    if (i < n) x[i] = (x[i] - g_stats[0]) * g_stats[1] + 1e-10f;
}

// ---------------- host-side launch helpers ----------------
template<int ACT, int OMODE, bool ACCUM, bool ADDROW>
static void launch_gemm(const uint32_t* Ah, const uint32_t* Al,
                        const uint32_t* Bh, const uint32_t* Bl,
                        const float* bias, const float* ra,
                        float* C, uint32_t* Chi, uint32_t* Clo,
                        int M, int N, int K2)
{
    constexpr int SM = 3 * 32768;
    auto kfn = gemm_tma<ACT, OMODE, ACCUM, ADDROW>;
    cudaFuncSetAttribute(kfn, cudaFuncAttributeMaxDynamicSharedMemorySize, SM);
    kfn<<<dim3(N / 128, M / 128), 128, SM>>>(Ah, Al, Bh, Bl, bias, ra, C, Chi, Clo, M, N, K2);
}

static void wsplit(const float* W, uint32_t* hi, uint32_t* lo, int K2, int N,
                   int layers = 1, size_t wstride = 0, size_t ostride = 0)
{
    wsplit_b<<<dim3(K2 / 32, N / 32, layers), dim3(32, 8)>>>(W, hi, lo, K2, N, wstride, ostride);
}

extern "C" void kernel_launch(void* const* d_in, const int* in_sizes, int n_in,
                              void* d_out, int out_size)
{
    const float* state  = (const float*)d_in[0];
    const float* fc1_w  = (const float*)d_in[1];
    const float* fc1_b  = (const float*)d_in[2];
    const float* fc2_w  = (const float*)d_in[3];
    const float* fc2_b  = (const float*)d_in[4];
    const float* fc3_w  = (const float*)d_in[5];
    const float* fc3_b  = (const float*)d_in[6];
    const float* fc4_w  = (const float*)d_in[7];
    const float* fc4_b  = (const float*)d_in[8];
    const float* fc5_w  = (const float*)d_in[9];
    const float* fc5_b  = (const float*)d_in[10];
    const float* pre_w  = (const float*)d_in[11];
    const float* pre_b  = (const float*)d_in[12];
    const float* pos_w  = (const float*)d_in[13];
    const float* enc_w  = (const float*)d_in[14];
    const float* enc_b  = (const float*)d_in[15];
    const float* ln1_g  = (const float*)d_in[16];
    const float* ln1_b  = (const float*)d_in[17];
    const float* ln2_g  = (const float*)d_in[18];
    const float* ln2_b  = (const float*)d_in[19];
    const float* res_w1 = (const float*)d_in[20];
    const float* res_b1 = (const float*)d_in[21];
    const float* res_w2 = (const float*)d_in[22];
    const float* res_b2 = (const float*)d_in[23];
    const float* out_w  = (const float*)d_in[24];
    const float* out_b  = (const float*)d_in[25];
    float* out = (float*)d_out;

    uint32_t *wh, *wl, *ah1, *al1, *ah2, *al2;
    float *x, *qkv, *att;
    cudaGetSymbolAddress((void**)&wh,  g_wh);
    cudaGetSymbolAddress((void**)&wl,  g_wl);
    cudaGetSymbolAddress((void**)&ah1, g_ah1);
    cudaGetSymbolAddress((void**)&al1, g_al1);
    cudaGetSymbolAddress((void**)&ah2, g_ah2);
    cudaGetSymbolAddress((void**)&al2, g_al2);
    cudaGetSymbolAddress((void**)&x,   g_x);
    cudaGetSymbolAddress((void**)&qkv, g_qkv);
    cudaGetSymbolAddress((void**)&att, g_att);

    const int M = TOK;

    // ---- weight transpose+splits -> stage-tiled [K2/16][N][16] ----
    wsplit(fc1_w, wh + W1_OFF,   wl + W1_OFF,   2048, 4096);
    wsplit(fc2_w, wh + W2_OFF,   wl + W2_OFF,   2048, 2048);
    wsplit(fc3_w, wh + W3_OFF,   wl + W3_OFF,   1024, 1024);
    wsplit(fc4_w, wh + W4_OFF,   wl + W4_OFF,    512,  512);
    wsplit(fc5_w, wh + W5_OFF,   wl + W5_OFF,    256,  256);
    wsplit(pre_w, wh + WPRE_OFF, wl + WPRE_OFF,  128,  256);
    wsplit(enc_w,  wh + WENC_OFF, wl + WENC_OFF, 128,  768, NBLK, 256 * 768,  98304);
    wsplit(res_w1, wh + WR1_OFF,  wl + WR1_OFF,  128, 1024, NBLK, 256 * 1024, 131072);
    wsplit(res_w2, wh + WR2_OFF,  wl + WR2_OFF,  512,  256, NBLK, 1024 * 256, 131072);
    wsplit(out_w, wh + WOUT_OFF, wl + WOUT_OFF, 128, 128);

    // ---- input split ----
    asplit_k<<<(M * 2048 + 255) / 256, 256>>>(state, ah1, al1, M, 2048);

    // ---- MLP stack (split in -> split out) ----
    launch_gemm<1, 1, false, false>(ah1, al1, wh + W1_OFF, wl + W1_OFF,
        fc1_b, nullptr, nullptr, ah2, al2, M, 4096, 2048);
    launch_gemm<1, 1, false, false>(ah2, al2, wh + W2_OFF, wl + W2_OFF,
        fc2_b, nullptr, nullptr, ah1, al1, M, 2048, 2048);
    launch_gemm<1, 1, false, false>(ah1, al1, wh + W3_OFF, wl + W3_OFF,
        fc3_b, nullptr, nullptr, ah2, al2, M, 1024, 1024);
    launch_gemm<1, 1, false, false>(ah2, al2, wh + W4_OFF, wl + W4_OFF,
        fc4_b, nullptr, nullptr, ah1, al1, M, 512, 512);
    launch_gemm<2, 1, false, false>(ah1, al1, wh + W5_OFF, wl + W5_OFF,
        fc5_b, nullptr, nullptr, ah2, al2, M, 256, 256);
    launch_gemm<0, 0, false, true>(ah2, al2, wh + WPRE_OFF, wl + WPRE_OFF,
        pre_b, pos_w, x, nullptr, nullptr, M, 256, 128);

    // ---- transformer blocks ----
    for (int l = 0; l < NBLK; l++) {
        ln_k<false, false, true><<<TOK, 128>>>(x, nullptr, ln1_g + l * DD, ln1_b + l * DD,
                                               nullptr, ah1, al1);
        launch_gemm<0, 0, false, false>(ah1, al1,
            wh + WENC_OFF + (size_t)l * 98304, wl + WENC_OFF + (size_t)l * 98304,
            enc_b + l * 3 * DD, nullptr, qkv, nullptr, nullptr, M, 768, 128);
        attn_k<<<dim3(SS / 128, HH, BB), 256>>>(qkv, att);
        ln_k<true, true, true><<<TOK, 128>>>(x, att, ln2_g + l * DD, ln2_b + l * DD,
                                             x, ah1, al1);
        launch_gemm<3, 1, false, false>(ah1, al1,
            wh + WR1_OFF + (size_t)l * 131072, wl + WR1_OFF + (size_t)l * 131072,
            res_b1 + l * 4 * DD, nullptr, nullptr, ah2, al2, M, 1024, 128);
        launch_gemm<0, 0, true, false>(ah2, al2,
            wh + WR2_OFF + (size_t)l * 131072, wl + WR2_OFF + (size_t)l * 131072,
            res_b2 + l * DD, nullptr, x, nullptr, nullptr, M, 256, 512);
    }

    // ---- output projection + global normalize ----
    asplit_k<<<(M * 128 + 255) / 256, 256>>>(x, ah1, al1, M, 128);
    launch_gemm<0, 0, false, false>(ah1, al1, wh + WOUT_OFF, wl + WOUT_OFF,
        out_b, nullptr, out, nullptr, nullptr, M, 128, 128);

    int n = TOK * 128;
    zero_red_k<<<1, 1>>>();
    reduce_k<<<256, 256>>>(out, n);
    stats_k<<<1, 1>>>(n);
    norm_k<<<(n + 255) / 256, 256>>>(out, n);
}

// round 12
// speedup vs baseline: 4.3671x; 1.0081x over previous
#include <cuda_runtime.h>
#include <cuda_bf16.h>
#include <math.h>
#include <stdint.h>

// Problem dims
#define BB 8
#define SS 512
#define DD 256
#define HH 8
#define DHH 32
#define NBLK 8
#define TOK (BB*SS)          // 4096 tokens

// ---------------- device scratch ----------------
// weight split arenas: stage-tiled [k-stage][N][16 u32], chunk-swizzled
#define W1_OFF   0u
#define W1_SZ    (2048u*4096u)
#define W2_OFF   (W1_OFF + W1_SZ)
#define W2_SZ    (2048u*2048u)
#define W3_OFF   (W2_OFF + W2_SZ)
#define W3_SZ    (1024u*1024u)
#define W4_OFF   (W3_OFF + W3_SZ)
#define W4_SZ    (512u*512u)
#define W5_OFF   (W4_OFF + W4_SZ)
#define W5_SZ    (256u*256u)
#define WPRE_OFF (W5_OFF + W5_SZ)
#define WPRE_SZ  (128u*256u)
#define WENC_OFF (WPRE_OFF + WPRE_SZ)
#define WENC_SZ  (1024u*768u)
#define WR1_OFF  (WENC_OFF + WENC_SZ)
#define WR1_SZ   (1024u*1024u)
#define WR2_OFF  (WR1_OFF + WR1_SZ)
#define WR2_SZ   (4096u*256u)
#define WOUT_OFF (WR2_OFF + WR2_SZ)
#define WOUT_SZ  (128u*128u)
#define WARENA   (WOUT_OFF + WOUT_SZ)

__device__ uint32_t g_wh[WARENA];
__device__ uint32_t g_wl[WARENA];

// activation split ping-pong arenas (stage-tiled), max 4096 x 2048 u32
__device__ uint32_t g_ah1[4096u*2048u];
__device__ uint32_t g_al1[4096u*2048u];
__device__ uint32_t g_ah2[4096u*2048u];
__device__ uint32_t g_al2[4096u*2048u];

__device__ float g_x  [TOK * DD];
__device__ float g_qkv[TOK * 3 * DD];
__device__ float g_att[TOK * DD];
__device__ double g_red[2];
__device__ float g_stats[2];

// ---------------- bf16 split helpers ----------------
__device__ __forceinline__ void split_pair(float x, float y, uint32_t& hi, uint32_t& lo)
{
    __nv_bfloat16 hx = __float2bfloat16_rn(x);
    __nv_bfloat16 hy = __float2bfloat16_rn(y);
    float rx = x - __bfloat162float(hx);
    float ry = y - __bfloat162float(hy);
    __nv_bfloat162 h2; h2.x = hx; h2.y = hy;
    __nv_bfloat162 l2; l2.x = __float2bfloat16_rn(rx); l2.y = __float2bfloat16_rn(ry);
    hi = *reinterpret_cast<uint32_t*>(&h2);
    lo = *reinterpret_cast<uint32_t*>(&l2);
}

__device__ __forceinline__ void mma16816(float* c, const uint32_t* a, const uint32_t* b)
{
    asm volatile(
        "mma.sync.aligned.m16n8k16.row.col.f32.bf16.bf16.f32 "
        "{%0,%1,%2,%3},{%4,%5,%6,%7},{%8,%9},{%0,%1,%2,%3};"
        : "+f"(c[0]), "+f"(c[1]), "+f"(c[2]), "+f"(c[3])
        : "r"(a[0]), "r"(a[1]), "r"(a[2]), "r"(a[3]), "r"(b[0]), "r"(b[1]));
}

__device__ __forceinline__ void ldsm4(uint32_t* r, uint32_t addr)
{
    asm volatile("ldmatrix.sync.aligned.m8n8.x4.shared.b16 {%0,%1,%2,%3},[%4];"
                 : "=r"(r[0]), "=r"(r[1]), "=r"(r[2]), "=r"(r[3]) : "r"(addr));
}

__device__ __forceinline__ uint32_t smem_u32(const void* p)
{
    uint32_t a;
    asm("{ .reg .u64 t; cvta.to.shared.u64 t, %1; cvt.u32.u64 %0, t; }" : "=r"(a) : "l"(p));
    return a;
}

__device__ __forceinline__ void mbar_init(uint32_t addr, uint32_t cnt)
{
    asm volatile("mbarrier.init.shared.b64 [%0], %1;" :: "r"(addr), "r"(cnt) : "memory");
}

__device__ __forceinline__ void mbar_expect_tx(uint32_t addr, uint32_t bytes)
{
    asm volatile("mbarrier.arrive.expect_tx.shared.b64 _, [%0], %1;"
                 :: "r"(addr), "r"(bytes) : "memory");
}

__device__ __forceinline__ void mbar_wait(uint32_t addr, uint32_t parity)
{
    uint32_t done;
    asm volatile("{\n\t.reg .pred p;\n\t"
        "mbarrier.try_wait.parity.acquire.cta.shared::cta.b64 p, [%1], %2;\n\t"
        "selp.b32 %0,1,0,p;\n\t}" : "=r"(done) : "r"(addr), "r"(parity) : "memory");
    while (!done) {
        asm volatile("{\n\t.reg .pred p;\n\t"
            "mbarrier.try_wait.parity.acquire.cta.shared::cta.b64 p, [%1], %2, 0x989680;\n\t"
            "selp.b32 %0,1,0,p;\n\t}" : "=r"(done) : "r"(addr), "r"(parity) : "memory");
    }
}

// 1D bulk async copy global -> shared, mbarrier transaction completion
__device__ __forceinline__ void bulkcp(uint32_t sdst, const void* gsrc, uint32_t bytes, uint32_t bar)
{
    asm volatile(
        "cp.async.bulk.shared::cluster.global.mbarrier::complete_tx::bytes [%0], [%1], %2, [%3];"
        :: "r"(sdst), "l"(gsrc), "r"(bytes), "r"(bar) : "memory");
}

// stage-tiled global index for pair kp of row m (rows-per-matrix = R)
// layout: [kp/16][m][16], 16B chunk swizzle c ^= (m>>1)&3
__device__ __forceinline__ size_t tile_idx(int m, int kp, int R)
{
    int sdx = kp >> 4, cc = (kp >> 2) & 3, ii = kp & 3;
    return ((size_t)sdx * R + m) * 16 + (size_t)(((cc ^ ((m >> 1) & 3)) << 2) + ii);
}

// ---------------- split kernels ----------------
// weight transpose+split: fp32 [K][N] -> hi/lo stage-tiled [K2/16][N][16]
__global__ void wsplit_b(const float* __restrict__ W0, uint32_t* __restrict__ hi0,
                         uint32_t* __restrict__ lo0, int K2, int N,
                         size_t wstride, size_t ostride)
{
    const float* W = W0 + (size_t)blockIdx.z * wstride;
    uint32_t* hi = hi0 + (size_t)blockIdx.z * ostride;
    uint32_t* lo = lo0 + (size_t)blockIdx.z * ostride;
    __shared__ uint32_t sh[32][33], sl[32][33];
    int kp0 = blockIdx.x * 32, n0 = blockIdx.y * 32;
    int tx = threadIdx.x, ty = threadIdx.y;   // (32,8)
#pragma unroll
    for (int i = ty; i < 32; i += 8) {
        int kp = kp0 + i;
        float f0 = W[(size_t)(2 * kp)     * N + n0 + tx];
        float f1 = W[(size_t)(2 * kp + 1) * N + n0 + tx];
        uint32_t h, l;
        split_pair(f0, f1, h, l);
        sh[i][tx] = h; sl[i][tx] = l;
    }
    __syncthreads();
#pragma unroll
    for (int j = ty; j < 32; j += 8) {
        int n = n0 + j;
        int kp = kp0 + tx;
        size_t o = tile_idx(n, kp, N);
        hi[o] = sh[tx][j];
        lo[o] = sl[tx][j];
    }
}

// activation: fp32 row-major [M][K] -> stage-tiled split
__global__ void asplit_k(const float* __restrict__ A, uint32_t* __restrict__ hi,
                         uint32_t* __restrict__ lo, int M, int K2)
{
    int idx = blockIdx.x * blockDim.x + threadIdx.x;
    if (idx >= M * K2) return;
    int m = idx / K2, kp = idx % K2;
    float2 v = reinterpret_cast<const float2*>(A)[idx];
    uint32_t h, l;
    split_pair(v.x, v.y, h, l);
    size_t o = tile_idx(m, kp, M);
    hi[o] = h; lo[o] = l;
}

// ---------------- tensor-core GEMM, bf16x3, TMA-bulk pipeline + ldmatrix ----------------
// A: hi/lo stage-tiled [K2/16][M][16], B: hi/lo stage-tiled [K2/16][N][16]
// Warp tiles WTM x WTN; split-outermost MMA order; TMA issued right after wait.
// OMODE: 0 = write fp32 C, 1 = write split stage-tiled Chi/Clo
template<int BM, int BN, int WY, int WX, int NBUF, int MAXCTA,
         int ACT, int OMODE, bool ACCUM, bool ADDROW>
__global__ __launch_bounds__(WY*WX*32, MAXCTA)
void gemm_w(const uint32_t* __restrict__ Ahg, const uint32_t* __restrict__ Alg,
            const uint32_t* __restrict__ Bhg, const uint32_t* __restrict__ Blg,
            const float* __restrict__ bias, const float* __restrict__ rowadd,
            float* __restrict__ C, uint32_t* __restrict__ Chi, uint32_t* __restrict__ Clo,
            int M, int N, int K2)
{
    constexpr int WTM = BM / WY, WTN = BN / WX;
    constexpr int MT = WTM / 16, NT = WTN / 8;
    constexpr int ASZ = BM * 64;         // bytes per A operand per stage
    constexpr int BSZ = BN * 64;         // bytes per B operand per stage
    constexpr int STG = 2 * (ASZ + BSZ);
    constexpr int PRE = NBUF - 1;

    extern __shared__ uint8_t dyn[];
    __shared__ __align__(8) uint64_t s_mbar[NBUF];

    const uint32_t dbase = smem_u32(dyn);
    const uint32_t mb = smem_u32(s_mbar);
    const int tid = threadIdx.x;
    const int lane = tid & 31;
    const int warp = tid >> 5;
    const int wy = warp / WX, wx = warp % WX;
    const int bm = blockIdx.y * BM, bn = blockIdx.x * BN;
    const int g = lane >> 2, t4 = lane & 3;

    if (tid == 0) {
#pragma unroll
        for (int i = 0; i < NBUF; i++) mbar_init(mb + i * 8, 1);
    }
    __syncthreads();

    const int NS = K2 >> 4;

    auto issue = [&](int s) {
        const uint32_t sb = dbase + (uint32_t)(s % NBUF) * STG;
        const uint32_t bar = mb + (uint32_t)(s % NBUF) * 8;
        mbar_expect_tx(bar, (uint32_t)STG);
        bulkcp(sb,                 Ahg + (size_t)(s * M + bm) * 16, ASZ, bar);
        bulkcp(sb + ASZ,           Alg + (size_t)(s * M + bm) * 16, ASZ, bar);
        bulkcp(sb + 2 * ASZ,       Bhg + (size_t)(s * N + bn) * 16, BSZ, bar);
        bulkcp(sb + 2 * ASZ + BSZ, Blg + (size_t)(s * N + bn) * 16, BSZ, bar);
    };

    float acc[MT][NT][4];
#pragma unroll
    for (int i = 0; i < MT; i++)
#pragma unroll
        for (int j = 0; j < NT; j++)
#pragma unroll
            for (int r = 0; r < 4; r++) acc[i][j][r] = 0.f;

    // per-thread ldsm row bases + swizzle keys
    uint32_t rA[MT]; int swA[MT];
    const int cbA = lane >> 4;
#pragma unroll
    for (int mt = 0; mt < MT; mt++) {
        int r = wy * WTM + mt * 16 + (lane & 15);
        rA[mt] = (uint32_t)r * 64;
        swA[mt] = (r >> 1) & 3;
    }
    const int q = lane >> 3;
    const int cbB = q & 1;
    uint32_t rB[NT / 2]; int swB[NT / 2];
#pragma unroll
    for (int p = 0; p < NT / 2; p++) {
        int r = wx * WTN + p * 16 + ((q >> 1) << 3) + (lane & 7);
        rB[p] = (uint32_t)r * 64;
        swB[p] = (r >> 1) & 3;
    }

    if (tid == 0) {
        int pre = NS < PRE ? NS : PRE;
        for (int s = 0; s < pre; s++) issue(s);
    }

    for (int s = 0; s < NS; s++) {
        const int slot = s % NBUF;
        mbar_wait(mb + slot * 8, (uint32_t)((s / NBUF) & 1));
        // slot (s-1)%NBUF was consumed + synced last iteration -> refill now
        if (tid == 0 && s + PRE < NS) issue(s + PRE);
        const uint32_t s0 = dbase + (uint32_t)slot * STG;
#pragma unroll
        for (int kk = 0; kk < 2; kk++) {
            uint32_t ah[MT][4], al[MT][4], bh[NT][2], bl[NT][2];
            const int k2c = kk * 2;
#pragma unroll
            for (int mt = 0; mt < MT; mt++) {
                uint32_t ch = (uint32_t)((k2c + cbA) ^ swA[mt]) * 16;
                ldsm4(ah[mt], s0 + rA[mt] + ch);
                ldsm4(al[mt], s0 + ASZ + rA[mt] + ch);
            }
#pragma unroll
            for (int p = 0; p < NT / 2; p++) {
                uint32_t ch = (uint32_t)((k2c + cbB) ^ swB[p]) * 16;
                uint32_t t[4];
                ldsm4(t, s0 + 2 * ASZ + rB[p] + ch);
                bh[2*p][0] = t[0]; bh[2*p][1] = t[1];
                bh[2*p+1][0] = t[2]; bh[2*p+1][1] = t[3];
                ldsm4(t, s0 + 2 * ASZ + BSZ + rB[p] + ch);
                bl[2*p][0] = t[0]; bl[2*p][1] = t[1];
                bl[2*p+1][0] = t[2]; bl[2*p+1][1] = t[3];
            }
            // split-outermost: accumulator reuse distance = MT*NT MMAs
#pragma unroll
            for (int mt = 0; mt < MT; mt++)
#pragma unroll
                for (int nt = 0; nt < NT; nt++)
                    mma16816(acc[mt][nt], ah[mt], bh[nt]);   // hi*hi
#pragma unroll
            for (int mt = 0; mt < MT; mt++)
#pragma unroll
                for (int nt = 0; nt < NT; nt++)
                    mma16816(acc[mt][nt], ah[mt], bl[nt]);   // hi*lo
#pragma unroll
            for (int mt = 0; mt < MT; mt++)
#pragma unroll
                for (int nt = 0; nt < NT; nt++)
                    mma16816(acc[mt][nt], al[mt], bh[nt]);   // lo*hi
        }
        __syncthreads();
    }

    // --- epilogue: pairs (col, col+1) ---
    auto epi = [&](int row, int col, float v0, float v1) {
        v0 += bias[col]; v1 += bias[col + 1];
        if (ADDROW) {
            const float* ra = rowadd + (size_t)(row % SS) * N + col;
            v0 += ra[0]; v1 += ra[1];
        }
        if (ACT == 1) { v0 = fmaxf(v0, 0.f); v1 = fmaxf(v1, 0.f); }
        else if (ACT == 2) { v0 = tanhf(v0); v1 = tanhf(v1); }
        else if (ACT == 3) {
            v0 = 0.5f * v0 * (1.f + erff(v0 * 0.70710678118654752f));
            v1 = 0.5f * v1 * (1.f + erff(v1 * 0.70710678118654752f));
        }
        if (OMODE == 0) {
            float* cp = C + (size_t)row * N + col;
            if (ACCUM) { cp[0] += v0; cp[1] += v1; }
            else       { float2 o; o.x = v0; o.y = v1; *reinterpret_cast<float2*>(cp) = o; }
        } else {
            uint32_t h, l;
            split_pair(v0, v1, h, l);
            size_t o = tile_idx(row, col >> 1, M);
            Chi[o] = h; Clo[o] = l;
        }
    };

#pragma unroll
    for (int mt = 0; mt < MT; mt++) {
        int r0 = bm + wy * WTM + mt * 16 + g;
#pragma unroll
        for (int nt = 0; nt < NT; nt++) {
            int c = bn + wx * WTN + nt * 8 + t4 * 2;
            epi(r0,     c, acc[mt][nt][0], acc[mt][nt][1]);
            epi(r0 + 8, c, acc[mt][nt][2], acc[mt][nt][3]);
        }
    }
}

// ---------------- LayerNorm over D=256, 128 threads x float2 ----------------
template<bool ADD, bool WF, bool WS>
__global__ void ln_k(const float* __restrict__ x, const float* __restrict__ add,
                     const float* __restrict__ g, const float* __restrict__ b,
                     float* __restrict__ outf, uint32_t* __restrict__ ohi,
                     uint32_t* __restrict__ olo)
{
    int t = blockIdx.x;
    int tid = threadIdx.x;    // 128
    float2 v = reinterpret_cast<const float2*>(x + (size_t)t * DD)[tid];
    if (ADD) {
        float2 a2 = reinterpret_cast<const float2*>(add + (size_t)t * DD)[tid];
        v.x += a2.x; v.y += a2.y;
    }
    float s = v.x + v.y, q = v.x * v.x + v.y * v.y;
#pragma unroll
    for (int o = 16; o > 0; o >>= 1) {
        s += __shfl_xor_sync(0xffffffffu, s, o);
        q += __shfl_xor_sync(0xffffffffu, q, o);
    }
    __shared__ float ws[4], wq[4];
    int w = tid >> 5, lane = tid & 31;
    if (lane == 0) { ws[w] = s; wq[w] = q; }
    __syncthreads();
    float ts = ws[0] + ws[1] + ws[2] + ws[3];
    float tq = wq[0] + wq[1] + wq[2] + wq[3];
    float mean = ts * (1.f / DD);
    float var  = tq * (1.f / DD) - mean * mean;
    float r = rsqrtf(var + 1e-5f);
    float2 gg = reinterpret_cast<const float2*>(g)[tid];
    float2 bb = reinterpret_cast<const float2*>(b)[tid];
    float y0 = (v.x - mean) * r * gg.x + bb.x;
    float y1 = (v.y - mean) * r * gg.y + bb.y;
    if (WF) {
        float2 o; o.x = y0; o.y = y1;
        reinterpret_cast<float2*>(outf + (size_t)t * DD)[tid] = o;
    }
    if (WS) {
        uint32_t h, l;
        split_pair(y0, y1, h, l);
        size_t o = tile_idx(t, tid, TOK);
        ohi[o] = h; olo[o] = l;
    }
}

// ---------------- flash-style causal attention ----------------
__global__ __launch_bounds__(256, 2)
void attn_k(const float* __restrict__ qkv, float* __restrict__ att)
{
    constexpr int KT = 64;
    constexpr int VST = 36;
    __shared__ float Ks[KT * VST];
    __shared__ float Vs[KT * VST];

    const int qt = blockIdx.x, h = blockIdx.y, b = blockIdx.z;
    const int tid = threadIdx.x;
    const int r = tid >> 1, half = tid & 1;
    const int qg = qt * 128 + r;

    const float* base = qkv + (size_t)(b * SS) * (3 * DD);
    const float scale = rsqrtf((float)DHH);

    float qreg[DHH];
    {
        const float4* qp = reinterpret_cast<const float4*>(base + (size_t)qg * (3 * DD) + h * DHH);
#pragma unroll
        for (int i = 0; i < 8; i++) {
            float4 f = qp[i];
            qreg[i*4+0] = f.x * scale; qreg[i*4+1] = f.y * scale;
            qreg[i*4+2] = f.z * scale; qreg[i*4+3] = f.w * scale;
        }
    }

    float m = -1e30f, lsum = 0.f;
    float o[DHH];
#pragma unroll
    for (int d = 0; d < DHH; d++) o[d] = 0.f;

    const int ntiles = (qt + 1) * 2;
    for (int kt = 0; kt < ntiles; kt++) {
#pragma unroll
        for (int it = 0; it < 2; it++) {
            int idx = tid + it * 256;
            int rr = idx >> 3, c = idx & 7;
            int k = kt * KT + rr;
            const float4* kp = reinterpret_cast<const float4*>(base + (size_t)k * (3 * DD) + DD + h * DHH);
            const float4* vp = reinterpret_cast<const float4*>(base + (size_t)k * (3 * DD) + 2 * DD + h * DHH);
            *reinterpret_cast<float4*>(&Ks[rr * VST + c * 4]) = kp[c];
            *reinterpret_cast<float4*>(&Vs[rr * VST + c * 4]) = vp[c];
        }
        __syncthreads();

        const int kbase = kt * KT + half * 32;
        if (kbase <= qg) {
            float p[32];
            float smax = -1e30f;
#pragma unroll 4
            for (int kk = 0; kk < 32; kk++) {
                const float* kr = &Ks[(half * 32 + kk) * VST];
                float dot = 0.f;
#pragma unroll
                for (int d = 0; d < DHH; d++) dot = fmaf(qreg[d], kr[d], dot);
                if (kbase + kk > qg) dot = -1e30f;
                p[kk] = dot;
                smax = fmaxf(smax, dot);
            }
            float newm = fmaxf(m, smax);
            float f = __expf(m - newm);
            float ls = 0.f;
#pragma unroll
            for (int kk = 0; kk < 32; kk++) {
                p[kk] = __expf(p[kk] - newm);
                ls += p[kk];
            }
            lsum = lsum * f + ls;
#pragma unroll
            for (int d = 0; d < DHH; d++) o[d] *= f;
#pragma unroll 4
            for (int kk = 0; kk < 32; kk++) {
                const float* vr = &Vs[(half * 32 + kk) * VST];
                float pk = p[kk];
#pragma unroll
                for (int d = 0; d < DHH; d++) o[d] = fmaf(pk, vr[d], o[d]);
            }
            m = newm;
        }
        __syncthreads();
    }

    float om = __shfl_xor_sync(0xffffffffu, m, 1);
    float nm = fmaxf(m, om);
    float fs = __expf(m - nm);
    float lS = lsum * fs;
    float lT = lS + __shfl_xor_sync(0xffffffffu, lS, 1);
    float inv = 1.f / lT;
    float* op = att + (size_t)(b * SS + qg) * DD + h * DHH;
#pragma unroll
    for (int d = 0; d < DHH; d++) {
        float oS = o[d] * fs;
        float oT = oS + __shfl_xor_sync(0xffffffffu, oS, 1);
        if (half == 0) op[d] = oT * inv;
    }
}

// ---------------- global normalize (mean / std ddof=1, + 1e-10) ----------------
__global__ void zero_red_k() { g_red[0] = 0.0; g_red[1] = 0.0; }

__global__ void reduce_k(const float* __restrict__ x, int n)
{
    double s = 0.0, q = 0.0;
    for (int i = blockIdx.x * blockDim.x + threadIdx.x; i < n; i += gridDim.x * blockDim.x) {
        double v = (double)x[i];
        s += v; q += v * v;
    }
#pragma unroll
    for (int o = 16; o > 0; o >>= 1) {
        s += __shfl_xor_sync(0xffffffffu, s, o);
        q += __shfl_xor_sync(0xffffffffu, q, o);
    }
    __shared__ double ws[8], wq[8];
    int w = threadIdx.x >> 5, lane = threadIdx.x & 31;
    if (lane == 0) { ws[w] = s; wq[w] = q; }
    __syncthreads();
    if (threadIdx.x == 0) {
        double ts = 0.0, tq = 0.0;
        for (int i = 0; i < (int)(blockDim.x / 32); i++) { ts += ws[i]; tq += wq[i]; }
        atomicAdd(&g_red[0], ts);
        atomicAdd(&g_red[1], tq);
    }
}

__global__ void stats_k(int n)
{
    double mean = g_red[0] / n;
    double var = (g_red[1] - (double)n * mean * mean) / (double)(n - 1);
    g_stats[0] = (float)mean;
    g_stats[1] = (float)(1.0 / sqrt(var));
}

__global__ void norm_k(float* __restrict__ x, int n)
{
    int i = blockIdx.x * blockDim.x + threadIdx.x;
    if (i < n) x[i] = (x[i] - g_stats[0]) * g_stats[1] + 1e-10f;
}

// ---------------- host-side launch helpers ----------------
template<int BM, int BN, int WY, int WX, int NBUF, int MAXCTA,
         int ACT, int OMODE, bool ACCUM, bool ADDROW>
static void launch_g(const uint32_t* Ah, const uint32_t* Al,
                     const uint32_t* Bh, const uint32_t* Bl,
                     const float* bias, const float* ra,
                     float* C, uint32_t* Chi, uint32_t* Clo,
                     int M, int N, int K2)
{
    constexpr int SM = NBUF * 2 * (BM * 64 + BN * 64);
    auto kfn = gemm_w<BM, BN, WY, WX, NBUF, MAXCTA, ACT, OMODE, ACCUM, ADDROW>;
    cudaFuncSetAttribute(kfn, cudaFuncAttributeMaxDynamicSharedMemorySize, SM);
    kfn<<<dim3(N / BN, M / BM), WY * WX * 32, SM>>>(Ah, Al, Bh, Bl, bias, ra, C, Chi, Clo, M, N, K2);
}

// big-N (N>=768): 128x256 tile, 8 warps, 4 buffers, 1 CTA/SM
#define GBIG(ACT, OM, AC, AR) launch_g<128, 256, 2, 4, 4, 1, ACT, OM, AC, AR>
// mid-N (N=512): 128x128 tile, 4 warps, 3 buffers, 2 CTA/SM
#define GMID(ACT, OM, AC, AR) launch_g<128, 128, 2, 2, 3, 2, ACT, OM, AC, AR>
// small-N (N<=256): 64x128 tile, 4 warps, 3 buffers, 2 CTA/SM
#define GSML(ACT, OM, AC, AR) launch_g<64, 128, 2, 2, 3, 2, ACT, OM, AC, AR>

static void wsplit(const float* W, uint32_t* hi, uint32_t* lo, int K2, int N,
                   int layers = 1, size_t wstride = 0, size_t ostride = 0)
{
    wsplit_b<<<dim3(K2 / 32, N / 32, layers), dim3(32, 8)>>>(W, hi, lo, K2, N, wstride, ostride);
}

extern "C" void kernel_launch(void* const* d_in, const int* in_sizes, int n_in,
                              void* d_out, int out_size)
{
    const float* state  = (const float*)d_in[0];
    const float* fc1_w  = (const float*)d_in[1];
    const float* fc1_b  = (const float*)d_in[2];
    const float* fc2_w  = (const float*)d_in[3];
    const float* fc2_b  = (const float*)d_in[4];
    const float* fc3_w  = (const float*)d_in[5];
    const float* fc3_b  = (const float*)d_in[6];
    const float* fc4_w  = (const float*)d_in[7];
    const float* fc4_b  = (const float*)d_in[8];
    const float* fc5_w  = (const float*)d_in[9];
    const float* fc5_b  = (const float*)d_in[10];
    const float* pre_w  = (const float*)d_in[11];
    const float* pre_b  = (const float*)d_in[12];
    const float* pos_w  = (const float*)d_in[13];
    const float* enc_w  = (const float*)d_in[14];
    const float* enc_b  = (const float*)d_in[15];
    const float* ln1_g  = (const float*)d_in[16];
    const float* ln1_b  = (const float*)d_in[17];
    const float* ln2_g  = (const float*)d_in[18];
    const float* ln2_b  = (const float*)d_in[19];
    const float* res_w1 = (const float*)d_in[20];
    const float* res_b1 = (const float*)d_in[21];
    const float* res_w2 = (const float*)d_in[22];
    const float* res_b2 = (const float*)d_in[23];
    const float* out_w  = (const float*)d_in[24];
    const float* out_b  = (const float*)d_in[25];
    float* out = (float*)d_out;

    uint32_t *wh, *wl, *ah1, *al1, *ah2, *al2;
    float *x, *qkv, *att;
    cudaGetSymbolAddress((void**)&wh,  g_wh);
    cudaGetSymbolAddress((void**)&wl,  g_wl);
    cudaGetSymbolAddress((void**)&ah1, g_ah1);
    cudaGetSymbolAddress((void**)&al1, g_al1);
    cudaGetSymbolAddress((void**)&ah2, g_ah2);
    cudaGetSymbolAddress((void**)&al2, g_al2);
    cudaGetSymbolAddress((void**)&x,   g_x);
    cudaGetSymbolAddress((void**)&qkv, g_qkv);
    cudaGetSymbolAddress((void**)&att, g_att);

    const int M = TOK;

    // ---- weight transpose+splits -> stage-tiled [K2/16][N][16] ----
    wsplit(fc1_w, wh + W1_OFF,   wl + W1_OFF,   2048, 4096);
    wsplit(fc2_w, wh + W2_OFF,   wl + W2_OFF,   2048, 2048);
    wsplit(fc3_w, wh + W3_OFF,   wl + W3_OFF,   1024, 1024);
    wsplit(fc4_w, wh + W4_OFF,   wl + W4_OFF,    512,  512);
    wsplit(fc5_w, wh + W5_OFF,   wl + W5_OFF,    256,  256);
    wsplit(pre_w, wh + WPRE_OFF, wl + WPRE_OFF,  128,  256);
    wsplit(enc_w,  wh + WENC_OFF, wl + WENC_OFF, 128,  768, NBLK, 256 * 768,  98304);
    wsplit(res_w1, wh + WR1_OFF,  wl + WR1_OFF,  128, 1024, NBLK, 256 * 1024, 131072);
    wsplit(res_w2, wh + WR2_OFF,  wl + WR2_OFF,  512,  256, NBLK, 1024 * 256, 131072);
    wsplit(out_w, wh + WOUT_OFF, wl + WOUT_OFF, 128, 128);

    // ---- input split ----
    asplit_k<<<(M * 2048 + 255) / 256, 256>>>(state, ah1, al1, M, 2048);

    // ---- MLP stack (split in -> split out) ----
    GBIG(1, 1, false, false)(ah1, al1, wh + W1_OFF, wl + W1_OFF,
        fc1_b, nullptr, nullptr, ah2, al2, M, 4096, 2048);
    GBIG(1, 1, false, false)(ah2, al2, wh + W2_OFF, wl + W2_OFF,
        fc2_b, nullptr, nullptr, ah1, al1, M, 2048, 2048);
    GBIG(1, 1, false, false)(ah1, al1, wh + W3_OFF, wl + W3_OFF,
        fc3_b, nullptr, nullptr, ah2, al2, M, 1024, 1024);
    GMID(1, 1, false, false)(ah2, al2, wh + W4_OFF, wl + W4_OFF,
        fc4_b, nullptr, nullptr, ah1, al1, M, 512, 512);
    GSML(2, 1, false, false)(ah1, al1, wh + W5_OFF, wl + W5_OFF,
        fc5_b, nullptr, nullptr, ah2, al2, M, 256, 256);
    GSML(0, 0, false, true)(ah2, al2, wh + WPRE_OFF, wl + WPRE_OFF,
        pre_b, pos_w, x, nullptr, nullptr, M, 256, 128);

    // ---- transformer blocks ----
    for (int l = 0; l < NBLK; l++) {
        ln_k<false, false, true><<<TOK, 128>>>(x, nullptr, ln1_g + l * DD, ln1_b + l * DD,
                                               nullptr, ah1, al1);
        GBIG(0, 0, false, false)(ah1, al1,
            wh + WENC_OFF + (size_t)l * 98304, wl + WENC_OFF + (size_t)l * 98304,
            enc_b + l * 3 * DD, nullptr, qkv, nullptr, nullptr, M, 768, 128);
        attn_k<<<dim3(SS / 128, HH, BB), 256>>>(qkv, att);
        ln_k<true, true, true><<<TOK, 128>>>(x, att, ln2_g + l * DD, ln2_b + l * DD,
                                             x, ah1, al1);
        GBIG(3, 1, false, false)(ah1, al1,
            wh + WR1_OFF + (size_t)l * 131072, wl + WR1_OFF + (size_t)l * 131072,
            res_b1 + l * 4 * DD, nullptr, nullptr, ah2, al2, M, 1024, 128);
        GSML(0, 0, true, false)(ah2, al2,
            wh + WR2_OFF + (size_t)l * 131072, wl + WR2_OFF + (size_t)l * 131072,
            res_b2 + l * DD, nullptr, x, nullptr, nullptr, M, 256, 512);
    }

    // ---- output projection + global normalize ----
    asplit_k<<<(M * 128 + 255) / 256, 256>>>(x, ah1, al1, M, 128);
    GSML(0, 0, false, false)(ah1, al1, wh + WOUT_OFF, wl + WOUT_OFF,
        out_b, nullptr, out, nullptr, nullptr, M, 128, 128);

    int n = TOK * 128;
    zero_red_k<<<1, 1>>>();
    reduce_k<<<256, 256>>>(out, n);
    stats_k<<<1, 1>>>(n);
    norm_k<<<(n + 255) / 256, 256>>>(out, n);
}